// round 1
// baseline (speedup 1.0000x reference)
#include <cuda_runtime.h>
#include <math.h>

// Problem constants
#define Bc 2
#define Lc 2048
#define Cc 1024
#define Hc 16
#define Dc 64
#define Mc (Bc*Lc)   // 4096 rows for the projection GEMMs

// Scratch (device globals: allocation-free rule)
__device__ float g_Qh[Bc*Hc*Lc*Dc];   // 16 MB, [B,H,L,D]
__device__ float g_Kh[Bc*Hc*Lc*Dc];   // 16 MB
__device__ float g_Vh[Bc*Hc*Lc*Dc];   // 16 MB
__device__ float g_Z [Bc*Lc*Cc];      // 16 MB, [B,L,C]

// ----------------------------------------------------------------------------
// GEMM: Y = X @ W + bias.  X:[4096,1024] row-major, W:[1024,1024] row-major.
// 128x128 block tile, BK=16, 256 threads, 8x8 micro-tile per thread.
// SPLITHEADS=1: write Y[m][n] to [B,H,L,D] layout (n = h*64+d, m = b*2048+l).
// ----------------------------------------------------------------------------
template<int SPLITHEADS>
__global__ void __launch_bounds__(256)
gemm_bias_kernel(const float* __restrict__ X, const float* __restrict__ W,
                 const float* __restrict__ bias, float* __restrict__ Y)
{
    const int Kd = 1024, Nd = 1024;
    __shared__ float As[16][132];   // [k][m], padded
    __shared__ float Bs[16][128];   // [k][n]

    const int t  = threadIdx.x;
    const int m0 = blockIdx.y * 128;
    const int n0 = blockIdx.x * 128;
    const int ty = t >> 4, tx = t & 15;

    float acc[8][8];
#pragma unroll
    for (int i = 0; i < 8; i++)
#pragma unroll
        for (int j = 0; j < 8; j++) acc[i][j] = 0.f;

    for (int k0 = 0; k0 < Kd; k0 += 16) {
        // Load A tile: 128 rows x 16 k  (512 float4)
#pragma unroll
        for (int u = 0; u < 2; u++) {
            int idx = t + u * 256;
            int r   = idx >> 2;
            int c4  = (idx & 3) * 4;
            float4 g = *(const float4*)&X[(size_t)(m0 + r) * Kd + k0 + c4];
            As[c4 + 0][r] = g.x;
            As[c4 + 1][r] = g.y;
            As[c4 + 2][r] = g.z;
            As[c4 + 3][r] = g.w;
        }
        // Load B tile: 16 k x 128 n  (512 float4)
#pragma unroll
        for (int u = 0; u < 2; u++) {
            int idx = t + u * 256;
            int kc  = idx >> 5;
            int c4  = (idx & 31) * 4;
            *(float4*)&Bs[kc][c4] =
                *(const float4*)&W[(size_t)(k0 + kc) * Nd + n0 + c4];
        }
        __syncthreads();

#pragma unroll
        for (int kc = 0; kc < 16; kc++) {
            float a[8], b[8];
            *(float4*)&a[0] = *(float4*)&As[kc][ty * 8];
            *(float4*)&a[4] = *(float4*)&As[kc][ty * 8 + 4];
            *(float4*)&b[0] = *(float4*)&Bs[kc][tx * 8];
            *(float4*)&b[4] = *(float4*)&Bs[kc][tx * 8 + 4];
#pragma unroll
            for (int i = 0; i < 8; i++)
#pragma unroll
                for (int j = 0; j < 8; j++)
                    acc[i][j] = fmaf(a[i], b[j], acc[i][j]);
        }
        __syncthreads();
    }

    // Epilogue
#pragma unroll
    for (int i = 0; i < 8; i++) {
        int m = m0 + ty * 8 + i;
#pragma unroll
        for (int j = 0; j < 8; j++) {
            int n = n0 + tx * 8 + j;
            float v = acc[i][j] + bias[n];
            if (SPLITHEADS) {
                int b = m >> 11, l = m & 2047;   // m = b*2048 + l
                int h = n >> 6,  d = n & 63;     // n = h*64 + d
                g_dummy_noop:;
                Y[(((size_t)(b * Hc + h)) * Lc + l) * Dc + d] = v;
            } else {
                Y[(size_t)m * Nd + n] = v;
            }
        }
    }
}

// ----------------------------------------------------------------------------
// Flash-style attention over Q,K,V in [B,H,L,D] layout.
// Block = 64 query rows x all keys (streamed in 64-key tiles), 256 threads,
// 4x4 micro-tiles, online softmax. Writes Z in [B,L,C] (c = h*64 + d).
// ----------------------------------------------------------------------------
__global__ void __launch_bounds__(256)
attn_kernel(const float* __restrict__ Q, const float* __restrict__ K,
            const float* __restrict__ V, const int* __restrict__ mask,
            float* __restrict__ Z)
{
    extern __shared__ float sm[];
    float* Qs  = sm;                 // 64 x 68
    float* Ks  = Qs + 64 * 68;       // 64 x 65  (reused as P after S phase)
    float* Vs  = Ks + 64 * 65;       // 64 x 68
    float* red = Vs + 64 * 68;       // 64 x 16
    float* m_s = red + 64 * 16;      // 64 row-max
    float* l_s = m_s + 64;           // 64 row-sum
    float* f_s = l_s + 64;           // 64 rescale factor

    const int t  = threadIdx.x;
    const int bh = blockIdx.y;           // b*H + h
    const int b  = bh >> 4;              // / H
    const int h  = bh & 15;
    const int q0 = blockIdx.x * 64;
    const int ty = t >> 4, tx = t & 15;

    const float* Qb = Q + (size_t)bh * Lc * Dc;
    const float* Kb = K + (size_t)bh * Lc * Dc;
    const float* Vb = V + (size_t)bh * Lc * Dc;
    const int*   Mb = mask + (size_t)b * Lc * Lc;

    if (t < 64) { m_s[t] = -INFINITY; l_s[t] = 0.f; }

    // Load Q tile [64 x 64]
#pragma unroll
    for (int u = 0; u < 4; u++) {
        int idx = t + u * 256;
        int r = idx >> 4, c4 = (idx & 15) * 4;
        float4 g = *(const float4*)&Qb[(size_t)(q0 + r) * Dc + c4];
        *(float4*)&Qs[r * 68 + c4] = g;
    }

    float o[4][4];
#pragma unroll
    for (int i = 0; i < 4; i++)
#pragma unroll
        for (int j = 0; j < 4; j++) o[i][j] = 0.f;

    __syncthreads();

    for (int kt = 0; kt < Lc; kt += 64) {
        // Load K and V tiles [64 x 64]
#pragma unroll
        for (int u = 0; u < 4; u++) {
            int idx = t + u * 256;
            int r = idx >> 4, c4 = (idx & 15) * 4;
            float4 kg = *(const float4*)&Kb[(size_t)(kt + r) * Dc + c4];
            Ks[r * 65 + c4 + 0] = kg.x;
            Ks[r * 65 + c4 + 1] = kg.y;
            Ks[r * 65 + c4 + 2] = kg.z;
            Ks[r * 65 + c4 + 3] = kg.w;
            float4 vg = *(const float4*)&Vb[(size_t)(kt + r) * Dc + c4];
            *(float4*)&Vs[r * 68 + c4] = vg;
        }
        __syncthreads();

        // S = Q K^T (4x4 per thread)
        float s[4][4];
#pragma unroll
        for (int i = 0; i < 4; i++)
#pragma unroll
            for (int j = 0; j < 4; j++) s[i][j] = 0.f;

#pragma unroll 8
        for (int k = 0; k < 64; k++) {
            float aq[4], bk[4];
#pragma unroll
            for (int i = 0; i < 4; i++) aq[i] = Qs[(ty * 4 + i) * 68 + k];
#pragma unroll
            for (int j = 0; j < 4; j++) bk[j] = Ks[(tx * 4 + j) * 65 + k];
#pragma unroll
            for (int i = 0; i < 4; i++)
#pragma unroll
                for (int j = 0; j < 4; j++)
                    s[i][j] = fmaf(aq[i], bk[j], s[i][j]);
        }

        // scale + mask, then per-row max partials
#pragma unroll
        for (int i = 0; i < 4; i++) {
            int q = q0 + ty * 4 + i;
            float rm = -INFINITY;
#pragma unroll
            for (int j = 0; j < 4; j++) {
                int kg = kt + tx * 4 + j;
                float sv = s[i][j] * 0.125f;          // 1/sqrt(64)
                if (Mb[(size_t)q * Lc + kg] == 0) sv = -1e9f;
                s[i][j] = sv;
                rm = fmaxf(rm, sv);
            }
            red[(ty * 4 + i) * 16 + tx] = rm;
        }
        __syncthreads();

        if (t < 64) {
            float mp = red[t * 16];
#pragma unroll
            for (int x = 1; x < 16; x++) mp = fmaxf(mp, red[t * 16 + x]);
            float mo = m_s[t];
            float mn = fmaxf(mo, mp);
            float f  = expf(mo - mn);                 // mo=-inf -> 0
            m_s[t] = mn; f_s[t] = f; l_s[t] *= f;
        }
        __syncthreads();

        // P = exp(S - m), rescale O, row-sum partials, store P over Ks
        float rs[4];
#pragma unroll
        for (int i = 0; i < 4; i++) {
            int qr = ty * 4 + i;
            float fi = f_s[qr];
            float mi = m_s[qr];
            rs[i] = 0.f;
#pragma unroll
            for (int j = 0; j < 4; j++) {
                o[i][j] *= fi;
                float p = expf(s[i][j] - mi);
                Ks[qr * 65 + tx * 4 + j] = p;
                rs[i] += p;
            }
            red[qr * 16 + tx] = rs[i];
        }
        __syncthreads();

        if (t < 64) {
            float acc = 0.f;
#pragma unroll
            for (int x = 0; x < 16; x++) acc += red[t * 16 + x];
            l_s[t] += acc;
        }

        // O += P @ V
#pragma unroll 8
        for (int kc = 0; kc < 64; kc++) {
            float ap[4];
#pragma unroll
            for (int i = 0; i < 4; i++) ap[i] = Ks[(ty * 4 + i) * 65 + kc];
            float4 bv = *(float4*)&Vs[kc * 68 + tx * 4];
#pragma unroll
            for (int i = 0; i < 4; i++) {
                o[i][0] = fmaf(ap[i], bv.x, o[i][0]);
                o[i][1] = fmaf(ap[i], bv.y, o[i][1]);
                o[i][2] = fmaf(ap[i], bv.z, o[i][2]);
                o[i][3] = fmaf(ap[i], bv.w, o[i][3]);
            }
        }
        __syncthreads();   // protects Ks/Vs reuse and publishes l_s
    }

    // Finalize: divide by row sums, write Z[b][q][h*64+d]
#pragma unroll
    for (int i = 0; i < 4; i++) {
        int qr = ty * 4 + i;
        float linv = 1.f / l_s[qr];
        size_t base = ((size_t)(b * Lc + q0 + qr)) * Cc + h * 64 + tx * 4;
#pragma unroll
        for (int j = 0; j < 4; j++)
            Z[base + j] = o[i][j] * linv;
    }
}

// ----------------------------------------------------------------------------
// Launcher
// ----------------------------------------------------------------------------
extern "C" void kernel_launch(void* const* d_in, const int* in_sizes, int n_in,
                              void* d_out, int out_size)
{
    const float* query = (const float*)d_in[0];
    const float* key_  = (const float*)d_in[1];
    const float* value = (const float*)d_in[2];
    const int*   mask  = (const int*)  d_in[3];
    const float* WQ = (const float*)d_in[4];
    const float* bQ = (const float*)d_in[5];
    const float* WK = (const float*)d_in[6];
    const float* bK = (const float*)d_in[7];
    const float* WV = (const float*)d_in[8];
    const float* bV = (const float*)d_in[9];
    const float* WO = (const float*)d_in[10];
    const float* bO = (const float*)d_in[11];
    float* out = (float*)d_out;

    void *pQ, *pK, *pV, *pZ;
    cudaGetSymbolAddress(&pQ, g_Qh);
    cudaGetSymbolAddress(&pK, g_Kh);
    cudaGetSymbolAddress(&pV, g_Vh);
    cudaGetSymbolAddress(&pZ, g_Z);

    const int attn_smem = (64 * 68 + 64 * 65 + 64 * 68 + 64 * 16 + 192) * 4;
    cudaFuncSetAttribute(attn_kernel,
                         cudaFuncAttributeMaxDynamicSharedMemorySize,
                         attn_smem);

    dim3 gemm_grid(Cc / 128, Mc / 128);   // (8, 32)
    gemm_bias_kernel<1><<<gemm_grid, 256>>>(query, WQ, bQ, (float*)pQ);
    gemm_bias_kernel<1><<<gemm_grid, 256>>>(key_,  WK, bK, (float*)pK);
    gemm_bias_kernel<1><<<gemm_grid, 256>>>(value, WV, bV, (float*)pV);

    dim3 attn_grid(Lc / 64, Bc * Hc);     // (32, 32)
    attn_kernel<<<attn_grid, 256, attn_smem>>>((const float*)pQ,
                                               (const float*)pK,
                                               (const float*)pV,
                                               mask, (float*)pZ);

    gemm_bias_kernel<0><<<gemm_grid, 256>>>((const float*)pZ, WO, bO, out);
}

// round 2
// speedup vs baseline: 1.0367x; 1.0367x over previous
#include <cuda_runtime.h>
#include <math.h>

// Problem constants
#define Bc 2
#define Lc 2048
#define Cc 1024
#define Hc 16
#define Dc 64
#define Mc (Bc*Lc)   // 4096 rows for the projection GEMMs

// Scratch (device globals: allocation-free rule)
__device__ float g_Qh[Bc*Hc*Lc*Dc];   // 16 MB, [B,H,L,D]
__device__ float g_Kh[Bc*Hc*Lc*Dc];   // 16 MB
__device__ float g_Vh[Bc*Hc*Lc*Dc];   // 16 MB
__device__ float g_Z [Bc*Lc*Cc];      // 16 MB, [B,L,C]

// ----------------------------------------------------------------------------
// GEMM: Y = X @ W + bias.  X:[4096,1024] row-major, W:[1024,1024] row-major.
// 128x128 block tile, BK=16, 256 threads, 8x8 micro-tile per thread.
// SPLITHEADS=1: write Y[m][n] to [B,H,L,D] layout (n = h*64+d, m = b*2048+l).
// ----------------------------------------------------------------------------
template<int SPLITHEADS>
__global__ void __launch_bounds__(256)
gemm_bias_kernel(const float* __restrict__ X, const float* __restrict__ W,
                 const float* __restrict__ bias, float* __restrict__ Y)
{
    const int Kd = 1024, Nd = 1024;
    __shared__ float As[16][132];   // [k][m], padded
    __shared__ float Bs[16][128];   // [k][n]

    const int t  = threadIdx.x;
    const int m0 = blockIdx.y * 128;
    const int n0 = blockIdx.x * 128;
    const int ty = t >> 4, tx = t & 15;

    float acc[8][8];
#pragma unroll
    for (int i = 0; i < 8; i++)
#pragma unroll
        for (int j = 0; j < 8; j++) acc[i][j] = 0.f;

    for (int k0 = 0; k0 < Kd; k0 += 16) {
#pragma unroll
        for (int u = 0; u < 2; u++) {
            int idx = t + u * 256;
            int r   = idx >> 2;
            int c4  = (idx & 3) * 4;
            float4 g = *(const float4*)&X[(size_t)(m0 + r) * Kd + k0 + c4];
            As[c4 + 0][r] = g.x;
            As[c4 + 1][r] = g.y;
            As[c4 + 2][r] = g.z;
            As[c4 + 3][r] = g.w;
        }
#pragma unroll
        for (int u = 0; u < 2; u++) {
            int idx = t + u * 256;
            int kc  = idx >> 5;
            int c4  = (idx & 31) * 4;
            *(float4*)&Bs[kc][c4] =
                *(const float4*)&W[(size_t)(k0 + kc) * Nd + n0 + c4];
        }
        __syncthreads();

#pragma unroll
        for (int kc = 0; kc < 16; kc++) {
            float a[8], b[8];
            *(float4*)&a[0] = *(float4*)&As[kc][ty * 8];
            *(float4*)&a[4] = *(float4*)&As[kc][ty * 8 + 4];
            *(float4*)&b[0] = *(float4*)&Bs[kc][tx * 8];
            *(float4*)&b[4] = *(float4*)&Bs[kc][tx * 8 + 4];
#pragma unroll
            for (int i = 0; i < 8; i++)
#pragma unroll
                for (int j = 0; j < 8; j++)
                    acc[i][j] = fmaf(a[i], b[j], acc[i][j]);
        }
        __syncthreads();
    }

#pragma unroll
    for (int i = 0; i < 8; i++) {
        int m = m0 + ty * 8 + i;
#pragma unroll
        for (int j = 0; j < 8; j++) {
            int n = n0 + tx * 8 + j;
            float v = acc[i][j] + bias[n];
            if (SPLITHEADS) {
                int b = m >> 11, l = m & 2047;   // m = b*2048 + l
                int h = n >> 6,  d = n & 63;     // n = h*64 + d
                Y[(((size_t)(b * Hc + h)) * Lc + l) * Dc + d] = v;
            } else {
                Y[(size_t)m * Nd + n] = v;
            }
        }
    }
}

// ----------------------------------------------------------------------------
// Fast 2^y for y <= 0 (FMA-only, no MUFU). Degree-6 Taylor on frac, rel err ~1.5e-5.
// ----------------------------------------------------------------------------
__device__ __forceinline__ float exp2p(float y)
{
    y = fmaxf(y, -126.f);
    float fl = floorf(y);
    float f  = y - fl;
    int   e  = (int)fl;
    float p  = 1.5407e-4f;                 // ln2^6/720
    p = fmaf(p, f, 0.0013333558f);         // ln2^5/120
    p = fmaf(p, f, 0.0096181291f);         // ln2^4/24
    p = fmaf(p, f, 0.0555041087f);         // ln2^3/6
    p = fmaf(p, f, 0.2402265070f);         // ln2^2/2
    p = fmaf(p, f, 0.6931471806f);         // ln2
    p = fmaf(p, f, 1.0f);
    return p * __int_as_float((e + 127) << 23);
}

// ----------------------------------------------------------------------------
// Flash attention v2: 64q x 64k tiles, 256 threads, 4x4 micro-tiles.
// log2-domain softmax (scale & mask folded), shuffle reductions,
// vectorized float4 smem access everywhere. P aliases the K tile.
// Score cols per thread: tx+16j (interleaved). Output d-cols: tx*4+j.
// ----------------------------------------------------------------------------
#define PIT 68

__global__ void __launch_bounds__(256, 2)
attn_kernel(const float* __restrict__ Q, const float* __restrict__ K,
            const float* __restrict__ V, const int* __restrict__ mask,
            float* __restrict__ Z)
{
    extern __shared__ float sm[];
    float* Qs = sm;                // 64 x 68
    float* Ks = Qs + 64 * PIT;     // 64 x 68, aliased as P in PV phase
    float* Vs = Ks + 64 * PIT;     // 64 x 68
    float* Ms = Vs + 64 * PIT;     // 64 x 68 mask bias (log2 domain)

    const int t  = threadIdx.x;
    const int ty = t >> 4, tx = t & 15;
    const int bh = blockIdx.y;
    const int b  = bh >> 4;
    const int h  = bh & 15;
    const int q0 = blockIdx.x * 64;

    const float* Qb = Q + (size_t)bh * Lc * Dc;
    const float* Kb = K + (size_t)bh * Lc * Dc;
    const float* Vb = V + (size_t)bh * Lc * Dc;
    const int*   Mb = mask + (size_t)b * Lc * Lc;

    const float SC = 0.125f * 1.4426950408889634f;   // (1/sqrt(D)) * log2(e)

    // Load Q tile
#pragma unroll
    for (int u = 0; u < 4; u++) {
        int idx = t + u * 256;
        int r = idx >> 4, c4 = (idx & 15) * 4;
        *(float4*)&Qs[r * PIT + c4] = *(const float4*)&Qb[(size_t)(q0 + r) * Dc + c4];
    }

    float m_r[4], l_r[4], o[4][4];
#pragma unroll
    for (int i = 0; i < 4; i++) {
        m_r[i] = -3.0e38f; l_r[i] = 0.f;
#pragma unroll
        for (int j = 0; j < 4; j++) o[i][j] = 0.f;
    }

    __syncthreads();

    for (int kt = 0; kt < Lc; kt += 64) {
        // Load K, V tiles and mask bias tile (all coalesced, vectorized)
#pragma unroll
        for (int u = 0; u < 4; u++) {
            int idx = t + u * 256;
            int r = idx >> 4, c4 = (idx & 15) * 4;
            *(float4*)&Ks[r * PIT + c4] = *(const float4*)&Kb[(size_t)(kt + r) * Dc + c4];
            *(float4*)&Vs[r * PIT + c4] = *(const float4*)&Vb[(size_t)(kt + r) * Dc + c4];
            int4 mm = *(const int4*)&Mb[(size_t)(q0 + r) * Lc + kt + c4];
            Ms[r * PIT + c4 + 0] = (float)(mm.x - 1) * 2.0e9f;
            Ms[r * PIT + c4 + 1] = (float)(mm.y - 1) * 2.0e9f;
            Ms[r * PIT + c4 + 2] = (float)(mm.z - 1) * 2.0e9f;
            Ms[r * PIT + c4 + 3] = (float)(mm.w - 1) * 2.0e9f;
        }
        __syncthreads();

        // ---- S = Q K^T (rows ty+16i, cols tx+16j), vectorized over d ----
        float s[4][4];
#pragma unroll
        for (int i = 0; i < 4; i++)
#pragma unroll
            for (int j = 0; j < 4; j++) s[i][j] = 0.f;

#pragma unroll
        for (int d4 = 0; d4 < 64; d4 += 4) {
            float4 a[4], bk[4];
#pragma unroll
            for (int i = 0; i < 4; i++) a[i]  = *(float4*)&Qs[(ty + 16 * i) * PIT + d4];
#pragma unroll
            for (int j = 0; j < 4; j++) bk[j] = *(float4*)&Ks[(tx + 16 * j) * PIT + d4];
#pragma unroll
            for (int i = 0; i < 4; i++)
#pragma unroll
                for (int j = 0; j < 4; j++) {
                    s[i][j] = fmaf(a[i].x, bk[j].x, s[i][j]);
                    s[i][j] = fmaf(a[i].y, bk[j].y, s[i][j]);
                    s[i][j] = fmaf(a[i].z, bk[j].z, s[i][j]);
                    s[i][j] = fmaf(a[i].w, bk[j].w, s[i][j]);
                }
        }

        // scale + mask bias (log2 domain), per-thread row max
        float tmax[4];
#pragma unroll
        for (int i = 0; i < 4; i++) {
            tmax[i] = -3.0e38f;
#pragma unroll
            for (int j = 0; j < 4; j++) {
                float sv = fmaf(s[i][j], SC, Ms[(ty + 16 * i) * PIT + tx + 16 * j]);
                s[i][j] = sv;
                tmax[i] = fmaxf(tmax[i], sv);
            }
        }
        // shuffle max across the 16 tx lanes (same warp half)
#pragma unroll
        for (int i = 0; i < 4; i++) {
            tmax[i] = fmaxf(tmax[i], __shfl_xor_sync(0xffffffffu, tmax[i], 1));
            tmax[i] = fmaxf(tmax[i], __shfl_xor_sync(0xffffffffu, tmax[i], 2));
            tmax[i] = fmaxf(tmax[i], __shfl_xor_sync(0xffffffffu, tmax[i], 4));
            tmax[i] = fmaxf(tmax[i], __shfl_xor_sync(0xffffffffu, tmax[i], 8));
        }

        float f[4];
#pragma unroll
        for (int i = 0; i < 4; i++) {
            float mn = fmaxf(m_r[i], tmax[i]);
            f[i] = exp2p(m_r[i] - mn);
            m_r[i] = mn;
            l_r[i] *= f[i];
        }

        __syncthreads();   // everyone done reading Ks before it becomes P

        // P = 2^(s - m); store over Ks; accumulate row sums; rescale o
        float rs[4];
#pragma unroll
        for (int i = 0; i < 4; i++) {
            rs[i] = 0.f;
#pragma unroll
            for (int j = 0; j < 4; j++) {
                float p = exp2p(s[i][j] - m_r[i]);
                Ks[(ty + 16 * i) * PIT + tx + 16 * j] = p;
                rs[i] += p;
                o[i][j] *= f[i];
            }
        }
#pragma unroll
        for (int i = 0; i < 4; i++) {
            rs[i] += __shfl_xor_sync(0xffffffffu, rs[i], 1);
            rs[i] += __shfl_xor_sync(0xffffffffu, rs[i], 2);
            rs[i] += __shfl_xor_sync(0xffffffffu, rs[i], 4);
            rs[i] += __shfl_xor_sync(0xffffffffu, rs[i], 8);
            l_r[i] += rs[i];
        }

        __syncthreads();   // P fully written

        // ---- O += P @ V (rows ty+16i, d-cols tx*4+j), vectorized over kc ----
#pragma unroll
        for (int kc = 0; kc < 64; kc += 4) {
            float4 pv[4];
#pragma unroll
            for (int i = 0; i < 4; i++) pv[i] = *(float4*)&Ks[(ty + 16 * i) * PIT + kc];
            float4 v0 = *(float4*)&Vs[(kc + 0) * PIT + tx * 4];
            float4 v1 = *(float4*)&Vs[(kc + 1) * PIT + tx * 4];
            float4 v2 = *(float4*)&Vs[(kc + 2) * PIT + tx * 4];
            float4 v3 = *(float4*)&Vs[(kc + 3) * PIT + tx * 4];
#pragma unroll
            for (int i = 0; i < 4; i++) {
                o[i][0] = fmaf(pv[i].x, v0.x, o[i][0]);
                o[i][1] = fmaf(pv[i].x, v0.y, o[i][1]);
                o[i][2] = fmaf(pv[i].x, v0.z, o[i][2]);
                o[i][3] = fmaf(pv[i].x, v0.w, o[i][3]);
                o[i][0] = fmaf(pv[i].y, v1.x, o[i][0]);
                o[i][1] = fmaf(pv[i].y, v1.y, o[i][1]);
                o[i][2] = fmaf(pv[i].y, v1.z, o[i][2]);
                o[i][3] = fmaf(pv[i].y, v1.w, o[i][3]);
                o[i][0] = fmaf(pv[i].z, v2.x, o[i][0]);
                o[i][1] = fmaf(pv[i].z, v2.y, o[i][1]);
                o[i][2] = fmaf(pv[i].z, v2.z, o[i][2]);
                o[i][3] = fmaf(pv[i].z, v2.w, o[i][3]);
                o[i][0] = fmaf(pv[i].w, v3.x, o[i][0]);
                o[i][1] = fmaf(pv[i].w, v3.y, o[i][1]);
                o[i][2] = fmaf(pv[i].w, v3.z, o[i][2]);
                o[i][3] = fmaf(pv[i].w, v3.w, o[i][3]);
            }
        }
        __syncthreads();   // done with P(=Ks)/Vs before next tile load
    }

    // Finalize: divide by row sums, write Z[b][q][h*64 + tx*4 + j] (float4)
#pragma unroll
    for (int i = 0; i < 4; i++) {
        int   qr   = ty + 16 * i;
        float linv = 1.f / l_r[i];
        float4 res;
        res.x = o[i][0] * linv;
        res.y = o[i][1] * linv;
        res.z = o[i][2] * linv;
        res.w = o[i][3] * linv;
        *(float4*)&g_Z[((size_t)(b * Lc + q0 + qr)) * Cc + h * 64 + tx * 4] = res;
    }
}

// ----------------------------------------------------------------------------
// Launcher
// ----------------------------------------------------------------------------
extern "C" void kernel_launch(void* const* d_in, const int* in_sizes, int n_in,
                              void* d_out, int out_size)
{
    const float* query = (const float*)d_in[0];
    const float* key_  = (const float*)d_in[1];
    const float* value = (const float*)d_in[2];
    const int*   mask  = (const int*)  d_in[3];
    const float* WQ = (const float*)d_in[4];
    const float* bQ = (const float*)d_in[5];
    const float* WK = (const float*)d_in[6];
    const float* bK = (const float*)d_in[7];
    const float* WV = (const float*)d_in[8];
    const float* bV = (const float*)d_in[9];
    const float* WO = (const float*)d_in[10];
    const float* bO = (const float*)d_in[11];
    float* out = (float*)d_out;

    void *pQ, *pK, *pV, *pZ;
    cudaGetSymbolAddress(&pQ, g_Qh);
    cudaGetSymbolAddress(&pK, g_Kh);
    cudaGetSymbolAddress(&pV, g_Vh);
    cudaGetSymbolAddress(&pZ, g_Z);

    const int attn_smem = 4 * 64 * PIT * 4;   // 69632 bytes
    cudaFuncSetAttribute(attn_kernel,
                         cudaFuncAttributeMaxDynamicSharedMemorySize,
                         attn_smem);

    dim3 gemm_grid(Cc / 128, Mc / 128);   // (8, 32)
    gemm_bias_kernel<1><<<gemm_grid, 256>>>(query, WQ, bQ, (float*)pQ);
    gemm_bias_kernel<1><<<gemm_grid, 256>>>(key_,  WK, bK, (float*)pK);
    gemm_bias_kernel<1><<<gemm_grid, 256>>>(value, WV, bV, (float*)pV);

    dim3 attn_grid(Lc / 64, Bc * Hc);     // (32, 32)
    attn_kernel<<<attn_grid, 256, attn_smem>>>((const float*)pQ,
                                               (const float*)pK,
                                               (const float*)pV,
                                               mask, nullptr);

    gemm_bias_kernel<0><<<gemm_grid, 256>>>((const float*)pZ, WO, bO, out);
}

// round 4
// speedup vs baseline: 1.4010x; 1.3514x over previous
#include <cuda_runtime.h>
#include <cuda_bf16.h>
#include <math.h>
#include <stdint.h>

// Problem constants
#define Bc 2
#define Lc 2048
#define Cc 1024
#define Hc 16
#define Dc 64
#define Mc (Bc*Lc)

// Scratch (device globals: allocation-free rule)
__device__ float g_Qh[Bc*Hc*Lc*Dc];
__device__ float g_Kh[Bc*Hc*Lc*Dc];
__device__ float g_Vh[Bc*Hc*Lc*Dc];
__device__ float g_Z [Bc*Lc*Cc];

// Pre-transposed, hi/lo-split weights: [N][K] bf16
__device__ __nv_bfloat16 g_WtQ_h[Cc*Cc], g_WtQ_l[Cc*Cc];
__device__ __nv_bfloat16 g_WtK_h[Cc*Cc], g_WtK_l[Cc*Cc];
__device__ __nv_bfloat16 g_WtV_h[Cc*Cc], g_WtV_l[Cc*Cc];
__device__ __nv_bfloat16 g_WtO_h[Cc*Cc], g_WtO_l[Cc*Cc];

// ============================================================================
// Helpers
// ============================================================================
__device__ __forceinline__ uint32_t smem_u32(const void* p) {
    uint32_t a;
    asm("{ .reg .u64 t; cvta.to.shared.u64 t, %1; cvt.u32.u64 %0, t; }"
        : "=r"(a) : "l"(p));
    return a;
}
#define SWZ128(off) ((off) ^ (((off) >> 3) & 0x70))

__device__ __forceinline__ void ldsm_x4(uint32_t* r, uint32_t addr) {
    asm volatile("ldmatrix.sync.aligned.m8n8.x4.shared.b16 {%0,%1,%2,%3}, [%4];"
                 : "=r"(r[0]), "=r"(r[1]), "=r"(r[2]), "=r"(r[3]) : "r"(addr));
}
__device__ __forceinline__ void mma_bf16(float* c, const uint32_t* a,
                                         const uint32_t* b) {
    asm volatile(
        "mma.sync.aligned.m16n8k16.row.col.f32.bf16.bf16.f32 "
        "{%0,%1,%2,%3}, {%4,%5,%6,%7}, {%8,%9}, {%0,%1,%2,%3};"
        : "+f"(c[0]), "+f"(c[1]), "+f"(c[2]), "+f"(c[3])
        : "r"(a[0]), "r"(a[1]), "r"(a[2]), "r"(a[3]), "r"(b[0]), "r"(b[1]));
}

// ============================================================================
// Prep: transpose + hi/lo split weights.  W[k][n] fp32 -> Th/Tl[n][k] bf16.
// ============================================================================
__global__ void wsplit_kernel(const float* __restrict__ W,
                              __nv_bfloat16* __restrict__ Th,
                              __nv_bfloat16* __restrict__ Tl)
{
    __shared__ float tile[32][33];
    int n0 = blockIdx.x * 32, k0 = blockIdx.y * 32;
    int tx = threadIdx.x, ty = threadIdx.y;
#pragma unroll
    for (int i = 0; i < 32; i += 8)
        tile[ty + i][tx] = W[(size_t)(k0 + ty + i) * Cc + n0 + tx];
    __syncthreads();
#pragma unroll
    for (int i = 0; i < 32; i += 8) {
        float x = tile[tx][ty + i];
        __nv_bfloat16 h = __float2bfloat16_rn(x);
        __nv_bfloat16 l = __float2bfloat16_rn(x - __bfloat162float(h));
        size_t idx = (size_t)(n0 + ty + i) * Cc + k0 + tx;
        Th[idx] = h; Tl[idx] = l;
    }
}

// ============================================================================
// HMMA GEMM: Y = X @ W + bias via 3-pass bf16 hi/lo split (mma.sync m16n8k16).
// X:[4096,1024] fp32. Bh/Bl:[1024,1024] bf16 = W^T (split). Tile 128x128, BK=64.
// 8 warps: warpM = wid&3 (32 m-rows each), warpN = wid>>2 (64 n-cols each).
// SW128 smem layout (128B rows), conflict-free for ldmatrix.
// ============================================================================
#define G_SMEM_TOTAL 65536

template<int SPLITHEADS>
__global__ void __launch_bounds__(256, 1)
gemm_mma_kernel(const float* __restrict__ X,
                const __nv_bfloat16* __restrict__ Bh_g,
                const __nv_bfloat16* __restrict__ Bl_g,
                const float* __restrict__ bias, float* __restrict__ Y)
{
    extern __shared__ char smem[];
    const uint32_t sb = smem_u32(smem);
    const uint32_t AH = 0, AL = 16384, BH = 32768, BL = 49152;

    const int t     = threadIdx.x;
    const int wid   = t >> 5;
    const int lane  = t & 31;
    const int warpM = wid & 3;
    const int warpN = wid >> 2;
    const int n0    = blockIdx.x * 128;
    const int m0    = blockIdx.y * 128;

    float acc[2][8][4];
#pragma unroll
    for (int mf = 0; mf < 2; mf++)
#pragma unroll
        for (int nf = 0; nf < 8; nf++)
#pragma unroll
            for (int e = 0; e < 4; e++) acc[mf][nf][e] = 0.f;

    // Per-lane ldmatrix row/chunk bases (constant across k-steps)
    const int mat   = lane >> 3;       // which 8x8 matrix this lane feeds
    const int r8    = lane & 7;
    // A: matrices (m0k0, m8k0, m0k8, m8k8)
    const int aRow0 = warpM * 32 + (mat & 1) * 8 + r8;   // + mf*16
    const int aKh   = mat >> 1;                          // k-half
    // B: matrices (n0k0, n0k8, n8k0, n8k8)
    const int bRow0 = warpN * 64 + (mat >> 1) * 8 + r8;  // + g*16
    const int bKh   = mat & 1;

    for (int s = 0; s < 16; s++) {
        const int k0 = s * 64;

        // --- fill A (fp32 -> bf16 hi/lo, SW128 128B rows) ---
#pragma unroll
        for (int u = 0; u < 4; u++) {
            int seg = t + u * 256;
            int r = seg >> 3, cseg = seg & 7;
            const float4* src = (const float4*)&X[(size_t)(m0 + r) * 1024 + k0 + cseg * 8];
            float4 x0 = src[0], x1 = src[1];
            float xs[8] = {x0.x, x0.y, x0.z, x0.w, x1.x, x1.y, x1.z, x1.w};
            __nv_bfloat16 hh[8], ll[8];
#pragma unroll
            for (int e = 0; e < 8; e++) {
                hh[e] = __float2bfloat16_rn(xs[e]);
                ll[e] = __float2bfloat16_rn(xs[e] - __bfloat162float(hh[e]));
            }
            uint32_t off = SWZ128((uint32_t)(r * 128 + cseg * 16));
            *(uint4*)(smem + AH + off) = *(uint4*)hh;
            *(uint4*)(smem + AL + off) = *(uint4*)ll;
        }
        // --- fill B hi/lo (bf16 [N][K] rows, SW128) ---
#pragma unroll
        for (int u = 0; u < 8; u++) {
            int seg  = t + u * 256;
            int half = seg >> 10;
            int s2   = seg & 1023;
            int r    = s2 >> 3, cseg = s2 & 7;
            const __nv_bfloat16* srcp = half ? Bl_g : Bh_g;
            uint4 v = *(const uint4*)&srcp[(size_t)(n0 + r) * 1024 + k0 + cseg * 8];
            uint32_t off = SWZ128((uint32_t)(r * 128 + cseg * 16));
            *(uint4*)(smem + (half ? BL : BH) + off) = v;
        }
        __syncthreads();

        // --- 4 k16-steps of MMAs ---
#pragma unroll
        for (int ks = 0; ks < 4; ks++) {
            uint32_t aH[2][4], aL[2][4];
#pragma unroll
            for (int mf = 0; mf < 2; mf++) {
                int row = aRow0 + mf * 16;
                uint32_t off = (uint32_t)(row * 128 +
                               (((2 * ks + aKh) ^ (row & 7)) * 16));
                ldsm_x4(aH[mf], sb + AH + off);
                ldsm_x4(aL[mf], sb + AL + off);
            }
            uint32_t bHf[4][4], bLf[4][4];
#pragma unroll
            for (int g = 0; g < 4; g++) {
                int row = bRow0 + g * 16;
                uint32_t off = (uint32_t)(row * 128 +
                               (((2 * ks + bKh) ^ (row & 7)) * 16));
                ldsm_x4(bHf[g], sb + BH + off);
                ldsm_x4(bLf[g], sb + BL + off);
            }
#pragma unroll
            for (int mf = 0; mf < 2; mf++)
#pragma unroll
                for (int nf = 0; nf < 8; nf++) {
                    const uint32_t* bh = &bHf[nf >> 1][(nf & 1) * 2];
                    const uint32_t* bl = &bLf[nf >> 1][(nf & 1) * 2];
                    mma_bf16(acc[mf][nf], aH[mf], bh);   // Ah*Bh
                    mma_bf16(acc[mf][nf], aH[mf], bl);   // Ah*Bl
                    mma_bf16(acc[mf][nf], aL[mf], bh);   // Al*Bh
                }
        }
        __syncthreads();
    }

    // --- epilogue: registers -> global with bias (float2 stores) ---
    const int rbase = lane >> 2;
    const int cpair = (lane & 3) * 2;
#pragma unroll
    for (int nf = 0; nf < 8; nf++) {
        int n = n0 + warpN * 64 + nf * 8 + cpair;
        float bx = __ldg(&bias[n]), by = __ldg(&bias[n + 1]);
#pragma unroll
        for (int mf = 0; mf < 2; mf++) {
            float* a = acc[mf][nf];
            int m = m0 + warpM * 32 + mf * 16 + rbase;
#pragma unroll
            for (int half = 0; half < 2; half++) {
                int mm = m + half * 8;
                float2 v = make_float2(a[half * 2 + 0] + bx, a[half * 2 + 1] + by);
                if (SPLITHEADS) {
                    int b = mm >> 11, l = mm & 2047;
                    int h = n >> 6,  d = n & 63;
                    *(float2*)&Y[(((size_t)(b * Hc + h)) * Lc + l) * Dc + d] = v;
                } else {
                    *(float2*)&Y[(size_t)mm * 1024 + n] = v;
                }
            }
        }
    }
}

// ============================================================================
// Fast 2^y for y <= 0 (FMA-only)
// ============================================================================
__device__ __forceinline__ float exp2p(float y)
{
    y = fmaxf(y, -126.f);
    float fl = floorf(y);
    float f  = y - fl;
    int   e  = (int)fl;
    float p  = 1.5407e-4f;
    p = fmaf(p, f, 0.0013333558f);
    p = fmaf(p, f, 0.0096181291f);
    p = fmaf(p, f, 0.0555041087f);
    p = fmaf(p, f, 0.2402265070f);
    p = fmaf(p, f, 0.6931471806f);
    p = fmaf(p, f, 1.0f);
    return p * __int_as_float((e + 127) << 23);
}

// ============================================================================
// Flash attention (unchanged from R2)
// ============================================================================
#define PIT 68

__global__ void __launch_bounds__(256, 2)
attn_kernel(const float* __restrict__ Q, const float* __restrict__ K,
            const float* __restrict__ V, const int* __restrict__ mask)
{
    extern __shared__ float sm[];
    float* Qs = sm;
    float* Ks = Qs + 64 * PIT;
    float* Vs = Ks + 64 * PIT;
    float* Ms = Vs + 64 * PIT;

    const int t  = threadIdx.x;
    const int ty = t >> 4, tx = t & 15;
    const int bh = blockIdx.y;
    const int b  = bh >> 4;
    const int h  = bh & 15;
    const int q0 = blockIdx.x * 64;

    const float* Qb = Q + (size_t)bh * Lc * Dc;
    const float* Kb = K + (size_t)bh * Lc * Dc;
    const float* Vb = V + (size_t)bh * Lc * Dc;
    const int*   Mb = mask + (size_t)b * Lc * Lc;

    const float SC = 0.125f * 1.4426950408889634f;

#pragma unroll
    for (int u = 0; u < 4; u++) {
        int idx = t + u * 256;
        int r = idx >> 4, c4 = (idx & 15) * 4;
        *(float4*)&Qs[r * PIT + c4] = *(const float4*)&Qb[(size_t)(q0 + r) * Dc + c4];
    }

    float m_r[4], l_r[4], o[4][4];
#pragma unroll
    for (int i = 0; i < 4; i++) {
        m_r[i] = -3.0e38f; l_r[i] = 0.f;
#pragma unroll
        for (int j = 0; j < 4; j++) o[i][j] = 0.f;
    }
    __syncthreads();

    for (int kt = 0; kt < Lc; kt += 64) {
#pragma unroll
        for (int u = 0; u < 4; u++) {
            int idx = t + u * 256;
            int r = idx >> 4, c4 = (idx & 15) * 4;
            *(float4*)&Ks[r * PIT + c4] = *(const float4*)&Kb[(size_t)(kt + r) * Dc + c4];
            *(float4*)&Vs[r * PIT + c4] = *(const float4*)&Vb[(size_t)(kt + r) * Dc + c4];
            int4 mm = *(const int4*)&Mb[(size_t)(q0 + r) * Lc + kt + c4];
            Ms[r * PIT + c4 + 0] = (float)(mm.x - 1) * 2.0e9f;
            Ms[r * PIT + c4 + 1] = (float)(mm.y - 1) * 2.0e9f;
            Ms[r * PIT + c4 + 2] = (float)(mm.z - 1) * 2.0e9f;
            Ms[r * PIT + c4 + 3] = (float)(mm.w - 1) * 2.0e9f;
        }
        __syncthreads();

        float s[4][4];
#pragma unroll
        for (int i = 0; i < 4; i++)
#pragma unroll
            for (int j = 0; j < 4; j++) s[i][j] = 0.f;

#pragma unroll
        for (int d4 = 0; d4 < 64; d4 += 4) {
            float4 a[4], bk[4];
#pragma unroll
            for (int i = 0; i < 4; i++) a[i]  = *(float4*)&Qs[(ty + 16 * i) * PIT + d4];
#pragma unroll
            for (int j = 0; j < 4; j++) bk[j] = *(float4*)&Ks[(tx + 16 * j) * PIT + d4];
#pragma unroll
            for (int i = 0; i < 4; i++)
#pragma unroll
                for (int j = 0; j < 4; j++) {
                    s[i][j] = fmaf(a[i].x, bk[j].x, s[i][j]);
                    s[i][j] = fmaf(a[i].y, bk[j].y, s[i][j]);
                    s[i][j] = fmaf(a[i].z, bk[j].z, s[i][j]);
                    s[i][j] = fmaf(a[i].w, bk[j].w, s[i][j]);
                }
        }

        float tmax[4];
#pragma unroll
        for (int i = 0; i < 4; i++) {
            tmax[i] = -3.0e38f;
#pragma unroll
            for (int j = 0; j < 4; j++) {
                float sv = fmaf(s[i][j], SC, Ms[(ty + 16 * i) * PIT + tx + 16 * j]);
                s[i][j] = sv;
                tmax[i] = fmaxf(tmax[i], sv);
            }
        }
#pragma unroll
        for (int i = 0; i < 4; i++) {
            tmax[i] = fmaxf(tmax[i], __shfl_xor_sync(0xffffffffu, tmax[i], 1));
            tmax[i] = fmaxf(tmax[i], __shfl_xor_sync(0xffffffffu, tmax[i], 2));
            tmax[i] = fmaxf(tmax[i], __shfl_xor_sync(0xffffffffu, tmax[i], 4));
            tmax[i] = fmaxf(tmax[i], __shfl_xor_sync(0xffffffffu, tmax[i], 8));
        }

        float f[4];
#pragma unroll
        for (int i = 0; i < 4; i++) {
            float mn = fmaxf(m_r[i], tmax[i]);
            f[i] = exp2p(m_r[i] - mn);
            m_r[i] = mn;
            l_r[i] *= f[i];
        }

        __syncthreads();

        float rs[4];
#pragma unroll
        for (int i = 0; i < 4; i++) {
            rs[i] = 0.f;
#pragma unroll
            for (int j = 0; j < 4; j++) {
                float p = exp2p(s[i][j] - m_r[i]);
                Ks[(ty + 16 * i) * PIT + tx + 16 * j] = p;
                rs[i] += p;
                o[i][j] *= f[i];
            }
        }
#pragma unroll
        for (int i = 0; i < 4; i++) {
            rs[i] += __shfl_xor_sync(0xffffffffu, rs[i], 1);
            rs[i] += __shfl_xor_sync(0xffffffffu, rs[i], 2);
            rs[i] += __shfl_xor_sync(0xffffffffu, rs[i], 4);
            rs[i] += __shfl_xor_sync(0xffffffffu, rs[i], 8);
            l_r[i] += rs[i];
        }

        __syncthreads();

#pragma unroll
        for (int kc = 0; kc < 64; kc += 4) {
            float4 pv[4];
#pragma unroll
            for (int i = 0; i < 4; i++) pv[i] = *(float4*)&Ks[(ty + 16 * i) * PIT + kc];
            float4 v0 = *(float4*)&Vs[(kc + 0) * PIT + tx * 4];
            float4 v1 = *(float4*)&Vs[(kc + 1) * PIT + tx * 4];
            float4 v2 = *(float4*)&Vs[(kc + 2) * PIT + tx * 4];
            float4 v3 = *(float4*)&Vs[(kc + 3) * PIT + tx * 4];
#pragma unroll
            for (int i = 0; i < 4; i++) {
                o[i][0] = fmaf(pv[i].x, v0.x, o[i][0]);
                o[i][1] = fmaf(pv[i].x, v0.y, o[i][1]);
                o[i][2] = fmaf(pv[i].x, v0.z, o[i][2]);
                o[i][3] = fmaf(pv[i].x, v0.w, o[i][3]);
                o[i][0] = fmaf(pv[i].y, v1.x, o[i][0]);
                o[i][1] = fmaf(pv[i].y, v1.y, o[i][1]);
                o[i][2] = fmaf(pv[i].y, v1.z, o[i][2]);
                o[i][3] = fmaf(pv[i].y, v1.w, o[i][3]);
                o[i][0] = fmaf(pv[i].z, v2.x, o[i][0]);
                o[i][1] = fmaf(pv[i].z, v2.y, o[i][1]);
                o[i][2] = fmaf(pv[i].z, v2.z, o[i][2]);
                o[i][3] = fmaf(pv[i].z, v2.w, o[i][3]);
                o[i][0] = fmaf(pv[i].w, v3.x, o[i][0]);
                o[i][1] = fmaf(pv[i].w, v3.y, o[i][1]);
                o[i][2] = fmaf(pv[i].w, v3.z, o[i][2]);
                o[i][3] = fmaf(pv[i].w, v3.w, o[i][3]);
            }
        }
        __syncthreads();
    }

#pragma unroll
    for (int i = 0; i < 4; i++) {
        int   qr   = ty + 16 * i;
        float linv = 1.f / l_r[i];
        float4 res;
        res.x = o[i][0] * linv;
        res.y = o[i][1] * linv;
        res.z = o[i][2] * linv;
        res.w = o[i][3] * linv;
        *(float4*)&g_Z[((size_t)(b * Lc + q0 + qr)) * Cc + h * 64 + tx * 4] = res;
    }
}

// ============================================================================
// Launcher
// ============================================================================
extern "C" void kernel_launch(void* const* d_in, const int* in_sizes, int n_in,
                              void* d_out, int out_size)
{
    const float* query = (const float*)d_in[0];
    const float* key_  = (const float*)d_in[1];
    const float* value = (const float*)d_in[2];
    const int*   mask  = (const int*)  d_in[3];
    const float* WQ = (const float*)d_in[4];
    const float* bQ = (const float*)d_in[5];
    const float* WK = (const float*)d_in[6];
    const float* bK = (const float*)d_in[7];
    const float* WV = (const float*)d_in[8];
    const float* bV = (const float*)d_in[9];
    const float* WO = (const float*)d_in[10];
    const float* bO = (const float*)d_in[11];
    float* out = (float*)d_out;

    void *pQ, *pK, *pV, *pZ;
    cudaGetSymbolAddress(&pQ, g_Qh);
    cudaGetSymbolAddress(&pK, g_Kh);
    cudaGetSymbolAddress(&pV, g_Vh);
    cudaGetSymbolAddress(&pZ, g_Z);
    void *wqh, *wql, *wkh, *wkl, *wvh, *wvl, *woh, *wol;
    cudaGetSymbolAddress(&wqh, g_WtQ_h); cudaGetSymbolAddress(&wql, g_WtQ_l);
    cudaGetSymbolAddress(&wkh, g_WtK_h); cudaGetSymbolAddress(&wkl, g_WtK_l);
    cudaGetSymbolAddress(&wvh, g_WtV_h); cudaGetSymbolAddress(&wvl, g_WtV_l);
    cudaGetSymbolAddress(&woh, g_WtO_h); cudaGetSymbolAddress(&wol, g_WtO_l);

    const int attn_smem = 4 * 64 * PIT * 4;
    cudaFuncSetAttribute(attn_kernel,
                         cudaFuncAttributeMaxDynamicSharedMemorySize, attn_smem);
    cudaFuncSetAttribute(gemm_mma_kernel<0>,
                         cudaFuncAttributeMaxDynamicSharedMemorySize, G_SMEM_TOTAL);
    cudaFuncSetAttribute(gemm_mma_kernel<1>,
                         cudaFuncAttributeMaxDynamicSharedMemorySize, G_SMEM_TOTAL);

    // Prep: transpose + split all 4 weight matrices
    dim3 wgrid(32, 32), wblk(32, 8);
    wsplit_kernel<<<wgrid, wblk>>>(WQ, (__nv_bfloat16*)wqh, (__nv_bfloat16*)wql);
    wsplit_kernel<<<wgrid, wblk>>>(WK, (__nv_bfloat16*)wkh, (__nv_bfloat16*)wkl);
    wsplit_kernel<<<wgrid, wblk>>>(WV, (__nv_bfloat16*)wvh, (__nv_bfloat16*)wvl);
    wsplit_kernel<<<wgrid, wblk>>>(WO, (__nv_bfloat16*)woh, (__nv_bfloat16*)wol);

    dim3 ggrid(Cc / 128, Mc / 128);   // (8, 32)
    gemm_mma_kernel<1><<<ggrid, 256, G_SMEM_TOTAL>>>(
        query, (const __nv_bfloat16*)wqh, (const __nv_bfloat16*)wql, bQ, (float*)pQ);
    gemm_mma_kernel<1><<<ggrid, 256, G_SMEM_TOTAL>>>(
        key_,  (const __nv_bfloat16*)wkh, (const __nv_bfloat16*)wkl, bK, (float*)pK);
    gemm_mma_kernel<1><<<ggrid, 256, G_SMEM_TOTAL>>>(
        value, (const __nv_bfloat16*)wvh, (const __nv_bfloat16*)wvl, bV, (float*)pV);

    dim3 attn_grid(Lc / 64, Bc * Hc);
    attn_kernel<<<attn_grid, 256, attn_smem>>>((const float*)pQ,
                                               (const float*)pK,
                                               (const float*)pV, mask);

    gemm_mma_kernel<0><<<ggrid, 256, G_SMEM_TOTAL>>>(
        (const float*)pZ, (const __nv_bfloat16*)woh, (const __nv_bfloat16*)wol, bO, out);
}

// round 5
// speedup vs baseline: 2.1513x; 1.5356x over previous
#include <cuda_runtime.h>
#include <cuda_bf16.h>
#include <math.h>
#include <stdint.h>

// Problem constants
#define Bc 2
#define Lc 2048
#define Cc 1024
#define Hc 16
#define Dc 64
#define Mc (Bc*Lc)

// Scratch (device globals: allocation-free rule)
__device__ float g_Qh[Bc*Hc*Lc*Dc];
__device__ float g_Kh[Bc*Hc*Lc*Dc];
__device__ float g_Vh[Bc*Hc*Lc*Dc];
__device__ float g_Z [Bc*Lc*Cc];
__device__ __nv_bfloat16 g_Mb[Bc*Lc*Lc];   // mask bias (log2 domain), 16.8MB

// Pre-transposed, hi/lo-split weights: [N][K] bf16
__device__ __nv_bfloat16 g_WtQ_h[Cc*Cc], g_WtQ_l[Cc*Cc];
__device__ __nv_bfloat16 g_WtK_h[Cc*Cc], g_WtK_l[Cc*Cc];
__device__ __nv_bfloat16 g_WtV_h[Cc*Cc], g_WtV_l[Cc*Cc];
__device__ __nv_bfloat16 g_WtO_h[Cc*Cc], g_WtO_l[Cc*Cc];

// ============================================================================
// Helpers
// ============================================================================
__device__ __forceinline__ uint32_t smem_u32(const void* p) {
    uint32_t a;
    asm("{ .reg .u64 t; cvta.to.shared.u64 t, %1; cvt.u32.u64 %0, t; }"
        : "=r"(a) : "l"(p));
    return a;
}
#define SWZ128(off) ((off) ^ (((off) >> 3) & 0x70))

__device__ __forceinline__ void ldsm_x4(uint32_t* r, uint32_t addr) {
    asm volatile("ldmatrix.sync.aligned.m8n8.x4.shared.b16 {%0,%1,%2,%3}, [%4];"
                 : "=r"(r[0]), "=r"(r[1]), "=r"(r[2]), "=r"(r[3]) : "r"(addr));
}
__device__ __forceinline__ void ldsm_x4_t(uint32_t* r, uint32_t addr) {
    asm volatile("ldmatrix.sync.aligned.m8n8.x4.trans.shared.b16 {%0,%1,%2,%3}, [%4];"
                 : "=r"(r[0]), "=r"(r[1]), "=r"(r[2]), "=r"(r[3]) : "r"(addr));
}
__device__ __forceinline__ void mma_bf16(float* c, const uint32_t* a,
                                         const uint32_t* b) {
    asm volatile(
        "mma.sync.aligned.m16n8k16.row.col.f32.bf16.bf16.f32 "
        "{%0,%1,%2,%3}, {%4,%5,%6,%7}, {%8,%9}, {%0,%1,%2,%3};"
        : "+f"(c[0]), "+f"(c[1]), "+f"(c[2]), "+f"(c[3])
        : "r"(a[0]), "r"(a[1]), "r"(a[2]), "r"(a[3]), "r"(b[0]), "r"(b[1]));
}
__device__ __forceinline__ uint32_t pack_bf16(float x, float y) {
    __nv_bfloat162 v = __floats2bfloat162_rn(x, y);
    return *(uint32_t*)&v;
}

// ============================================================================
// Prep: transpose + hi/lo split weights.  W[k][n] fp32 -> Th/Tl[n][k] bf16.
// ============================================================================
__global__ void wsplit_kernel(const float* __restrict__ W,
                              __nv_bfloat16* __restrict__ Th,
                              __nv_bfloat16* __restrict__ Tl)
{
    __shared__ float tile[32][33];
    int n0 = blockIdx.x * 32, k0 = blockIdx.y * 32;
    int tx = threadIdx.x, ty = threadIdx.y;
#pragma unroll
    for (int i = 0; i < 32; i += 8)
        tile[ty + i][tx] = W[(size_t)(k0 + ty + i) * Cc + n0 + tx];
    __syncthreads();
#pragma unroll
    for (int i = 0; i < 32; i += 8) {
        float x = tile[tx][ty + i];
        __nv_bfloat16 h = __float2bfloat16_rn(x);
        __nv_bfloat16 l = __float2bfloat16_rn(x - __bfloat162float(h));
        size_t idx = (size_t)(n0 + ty + i) * Cc + k0 + tx;
        Th[idx] = h; Tl[idx] = l;
    }
}

// Prep: mask int -> bf16 additive bias (log2 domain).  (m-1)*2e9
__global__ void maskprep_kernel(const int* __restrict__ m,
                                __nv_bfloat16* __restrict__ out)
{
    int i = (blockIdx.x * 256 + threadIdx.x) * 4;
    int4 v = *(const int4*)&m[i];
    __nv_bfloat162 a, b2;
    a.x  = __float2bfloat16_rn((float)(v.x - 1) * 2.0e9f);
    a.y  = __float2bfloat16_rn((float)(v.y - 1) * 2.0e9f);
    b2.x = __float2bfloat16_rn((float)(v.z - 1) * 2.0e9f);
    b2.y = __float2bfloat16_rn((float)(v.w - 1) * 2.0e9f);
    uint2 o; o.x = *(uint32_t*)&a; o.y = *(uint32_t*)&b2;
    *(uint2*)&out[i] = o;
}

// ============================================================================
// HMMA GEMM (unchanged from R4): Y = X @ W + bias, 3-pass bf16 hi/lo split.
// ============================================================================
#define G_SMEM_TOTAL 65536

template<int SPLITHEADS>
__global__ void __launch_bounds__(256, 1)
gemm_mma_kernel(const float* __restrict__ X,
                const __nv_bfloat16* __restrict__ Bh_g,
                const __nv_bfloat16* __restrict__ Bl_g,
                const float* __restrict__ bias, float* __restrict__ Y)
{
    extern __shared__ char smem[];
    const uint32_t sb = smem_u32(smem);
    const uint32_t AH = 0, AL = 16384, BH = 32768, BL = 49152;

    const int t     = threadIdx.x;
    const int wid   = t >> 5;
    const int lane  = t & 31;
    const int warpM = wid & 3;
    const int warpN = wid >> 2;
    const int n0    = blockIdx.x * 128;
    const int m0    = blockIdx.y * 128;

    float acc[2][8][4];
#pragma unroll
    for (int mf = 0; mf < 2; mf++)
#pragma unroll
        for (int nf = 0; nf < 8; nf++)
#pragma unroll
            for (int e = 0; e < 4; e++) acc[mf][nf][e] = 0.f;

    const int mat   = lane >> 3;
    const int r8    = lane & 7;
    const int aRow0 = warpM * 32 + (mat & 1) * 8 + r8;
    const int aKh   = mat >> 1;
    const int bRow0 = warpN * 64 + (mat >> 1) * 8 + r8;
    const int bKh   = mat & 1;

    for (int s = 0; s < 16; s++) {
        const int k0 = s * 64;
#pragma unroll
        for (int u = 0; u < 4; u++) {
            int seg = t + u * 256;
            int r = seg >> 3, cseg = seg & 7;
            const float4* src = (const float4*)&X[(size_t)(m0 + r) * 1024 + k0 + cseg * 8];
            float4 x0 = src[0], x1 = src[1];
            float xs[8] = {x0.x, x0.y, x0.z, x0.w, x1.x, x1.y, x1.z, x1.w};
            __nv_bfloat16 hh[8], ll[8];
#pragma unroll
            for (int e = 0; e < 8; e++) {
                hh[e] = __float2bfloat16_rn(xs[e]);
                ll[e] = __float2bfloat16_rn(xs[e] - __bfloat162float(hh[e]));
            }
            uint32_t off = SWZ128((uint32_t)(r * 128 + cseg * 16));
            *(uint4*)(smem + AH + off) = *(uint4*)hh;
            *(uint4*)(smem + AL + off) = *(uint4*)ll;
        }
#pragma unroll
        for (int u = 0; u < 8; u++) {
            int seg  = t + u * 256;
            int half = seg >> 10;
            int s2   = seg & 1023;
            int r    = s2 >> 3, cseg = s2 & 7;
            const __nv_bfloat16* srcp = half ? Bl_g : Bh_g;
            uint4 v = *(const uint4*)&srcp[(size_t)(n0 + r) * 1024 + k0 + cseg * 8];
            uint32_t off = SWZ128((uint32_t)(r * 128 + cseg * 16));
            *(uint4*)(smem + (half ? BL : BH) + off) = v;
        }
        __syncthreads();

#pragma unroll
        for (int ks = 0; ks < 4; ks++) {
            uint32_t aH[2][4], aL[2][4];
#pragma unroll
            for (int mf = 0; mf < 2; mf++) {
                int row = aRow0 + mf * 16;
                uint32_t off = (uint32_t)(row * 128 +
                               (((2 * ks + aKh) ^ (row & 7)) * 16));
                ldsm_x4(aH[mf], sb + AH + off);
                ldsm_x4(aL[mf], sb + AL + off);
            }
            uint32_t bHf[4][4], bLf[4][4];
#pragma unroll
            for (int g = 0; g < 4; g++) {
                int row = bRow0 + g * 16;
                uint32_t off = (uint32_t)(row * 128 +
                               (((2 * ks + bKh) ^ (row & 7)) * 16));
                ldsm_x4(bHf[g], sb + BH + off);
                ldsm_x4(bLf[g], sb + BL + off);
            }
#pragma unroll
            for (int mf = 0; mf < 2; mf++)
#pragma unroll
                for (int nf = 0; nf < 8; nf++) {
                    const uint32_t* bh = &bHf[nf >> 1][(nf & 1) * 2];
                    const uint32_t* bl = &bLf[nf >> 1][(nf & 1) * 2];
                    mma_bf16(acc[mf][nf], aH[mf], bh);
                    mma_bf16(acc[mf][nf], aH[mf], bl);
                    mma_bf16(acc[mf][nf], aL[mf], bh);
                }
        }
        __syncthreads();
    }

    const int rbase = lane >> 2;
    const int cpair = (lane & 3) * 2;
#pragma unroll
    for (int nf = 0; nf < 8; nf++) {
        int n = n0 + warpN * 64 + nf * 8 + cpair;
        float bx = __ldg(&bias[n]), by = __ldg(&bias[n + 1]);
#pragma unroll
        for (int mf = 0; mf < 2; mf++) {
            float* a = acc[mf][nf];
            int m = m0 + warpM * 32 + mf * 16 + rbase;
#pragma unroll
            for (int half = 0; half < 2; half++) {
                int mm = m + half * 8;
                float2 v = make_float2(a[half * 2 + 0] + bx, a[half * 2 + 1] + by);
                if (SPLITHEADS) {
                    int b = mm >> 11, l = mm & 2047;
                    int h = n >> 6,  d = n & 63;
                    *(float2*)&Y[(((size_t)(b * Hc + h)) * Lc + l) * Dc + d] = v;
                } else {
                    *(float2*)&Y[(size_t)mm * 1024 + n] = v;
                }
            }
        }
    }
}

// ============================================================================
// Fast 2^y for y <= 0 (FMA-only)
// ============================================================================
__device__ __forceinline__ float exp2p(float y)
{
    y = fmaxf(y, -126.f);
    float fl = floorf(y);
    float f  = y - fl;
    int   e  = (int)fl;
    float p  = 1.5407e-4f;
    p = fmaf(p, f, 0.0013333558f);
    p = fmaf(p, f, 0.0096181291f);
    p = fmaf(p, f, 0.0555041087f);
    p = fmaf(p, f, 0.2402265070f);
    p = fmaf(p, f, 0.6931471806f);
    p = fmaf(p, f, 1.0f);
    return p * __int_as_float((e + 127) << 23);
}

// ============================================================================
// HMMA flash attention. Block = 128 q rows, 8 warps (16 q-rows/warp),
// K/V streamed in 64-key tiles. Q/K/V split bf16 hi/lo (3 MMA passes each).
// P stays in registers (C-fragment == A-fragment layout). V via ldmatrix.trans.
// ============================================================================
#define ATT_QH 0
#define ATT_QL 16384
#define ATT_KH 32768
#define ATT_KL 40960
#define ATT_VH 49152
#define ATT_VL 57344
#define ATT_MS 65536                     // bf16 [128][72] (144B rows)
#define ATT_SMEM (65536 + 128*144)       // 83968

__global__ void __launch_bounds__(256, 1)
attn_mma_kernel(const float* __restrict__ Q, const float* __restrict__ K,
                const float* __restrict__ V, const __nv_bfloat16* __restrict__ Mb,
                float* __restrict__ Z)
{
    extern __shared__ char smem[];
    const uint32_t sb = smem_u32(smem);
    const int t  = threadIdx.x;
    const int w  = t >> 5;
    const int l  = t & 31;
    const int bh = blockIdx.y;
    const int b  = bh >> 4;
    const int h  = bh & 15;
    const int q0 = blockIdx.x * 128;

    const float* Qb = Q + (size_t)bh * Lc * Dc;
    const float* Kb = K + (size_t)bh * Lc * Dc;
    const float* Vb = V + (size_t)bh * Lc * Dc;
    const __nv_bfloat16* Mbb = Mb + ((size_t)b * Lc + q0) * Lc;

    const float SC = 0.125f * 1.4426950408889634f;

    const int mat = l >> 3;
    const int r8  = l & 7;
    const int gr  = l >> 2;

    // Load Q tile [128 x 64] -> bf16 hi/lo, SW128
#pragma unroll
    for (int u = 0; u < 4; u++) {
        int seg = t + u * 256;
        int r = seg >> 3, cseg = seg & 7;
        const float4* src = (const float4*)&Qb[(size_t)(q0 + r) * Dc + cseg * 8];
        float4 x0 = src[0], x1 = src[1];
        float xs[8] = {x0.x, x0.y, x0.z, x0.w, x1.x, x1.y, x1.z, x1.w};
        __nv_bfloat16 hh[8], ll[8];
#pragma unroll
        for (int e = 0; e < 8; e++) {
            hh[e] = __float2bfloat16_rn(xs[e]);
            ll[e] = __float2bfloat16_rn(xs[e] - __bfloat162float(hh[e]));
        }
        uint32_t off = SWZ128((uint32_t)(r * 128 + cseg * 16));
        *(uint4*)(smem + ATT_QH + off) = *(uint4*)hh;
        *(uint4*)(smem + ATT_QL + off) = *(uint4*)ll;
    }

    float accO[8][4];
#pragma unroll
    for (int nf = 0; nf < 8; nf++)
#pragma unroll
        for (int e = 0; e < 4; e++) accO[nf][e] = 0.f;
    float m0r = -3.0e38f, m1r = -3.0e38f, l0r = 0.f, l1r = 0.f;

    for (int kt = 0; kt < Lc; kt += 64) {
        // --- stage K, V (fp32 -> hi/lo bf16, SW128) and mask bias rows ---
#pragma unroll
        for (int u = 0; u < 2; u++) {
            int seg = t + u * 256;
            int r = seg >> 3, cseg = seg & 7;
            uint32_t off = SWZ128((uint32_t)(r * 128 + cseg * 16));
            {
                const float4* src = (const float4*)&Kb[(size_t)(kt + r) * Dc + cseg * 8];
                float4 x0 = src[0], x1 = src[1];
                float xs[8] = {x0.x, x0.y, x0.z, x0.w, x1.x, x1.y, x1.z, x1.w};
                __nv_bfloat16 hh[8], ll[8];
#pragma unroll
                for (int e = 0; e < 8; e++) {
                    hh[e] = __float2bfloat16_rn(xs[e]);
                    ll[e] = __float2bfloat16_rn(xs[e] - __bfloat162float(hh[e]));
                }
                *(uint4*)(smem + ATT_KH + off) = *(uint4*)hh;
                *(uint4*)(smem + ATT_KL + off) = *(uint4*)ll;
            }
            {
                const float4* src = (const float4*)&Vb[(size_t)(kt + r) * Dc + cseg * 8];
                float4 x0 = src[0], x1 = src[1];
                float xs[8] = {x0.x, x0.y, x0.z, x0.w, x1.x, x1.y, x1.z, x1.w};
                __nv_bfloat16 hh[8], ll[8];
#pragma unroll
                for (int e = 0; e < 8; e++) {
                    hh[e] = __float2bfloat16_rn(xs[e]);
                    ll[e] = __float2bfloat16_rn(xs[e] - __bfloat162float(hh[e]));
                }
                *(uint4*)(smem + ATT_VH + off) = *(uint4*)hh;
                *(uint4*)(smem + ATT_VL + off) = *(uint4*)ll;
            }
        }
#pragma unroll
        for (int u = 0; u < 4; u++) {
            int seg = t + u * 256;
            int r = seg >> 3, cseg = seg & 7;
            uint4 v = *(const uint4*)&Mbb[(size_t)r * Lc + kt + cseg * 8];
            *(uint4*)(smem + ATT_MS + r * 144 + cseg * 16) = v;
        }
        __syncthreads();

        // --- S = Q K^T (3-pass split) ---
        float accS[8][4];
#pragma unroll
        for (int nf = 0; nf < 8; nf++)
#pragma unroll
            for (int e = 0; e < 4; e++) accS[nf][e] = 0.f;

#pragma unroll
        for (int kf = 0; kf < 4; kf++) {
            uint32_t qh[4], ql[4];
            {
                int row = w * 16 + (mat & 1) * 8 + r8;
                int chk = kf * 2 + (mat >> 1);
                uint32_t off = (uint32_t)(row * 128 + ((chk ^ (row & 7)) * 16));
                ldsm_x4(qh, sb + ATT_QH + off);
                ldsm_x4(ql, sb + ATT_QL + off);
            }
#pragma unroll
            for (int g = 0; g < 4; g++) {
                uint32_t kh[4], kl[4];
                int row = g * 16 + (mat >> 1) * 8 + r8;
                int chk = kf * 2 + (mat & 1);
                uint32_t off = (uint32_t)(row * 128 + ((chk ^ (row & 7)) * 16));
                ldsm_x4(kh, sb + ATT_KH + off);
                ldsm_x4(kl, sb + ATT_KL + off);
                mma_bf16(accS[2 * g],     qh, kh);
                mma_bf16(accS[2 * g],     qh, kl);
                mma_bf16(accS[2 * g],     ql, kh);
                mma_bf16(accS[2 * g + 1], qh, kh + 2);
                mma_bf16(accS[2 * g + 1], qh, kl + 2);
                mma_bf16(accS[2 * g + 1], ql, kh + 2);
            }
        }

        // --- softmax (fp32, log2 domain, in registers) ---
        const int rw0 = w * 16 + gr;
        float t0 = -3.0e38f, t1 = -3.0e38f;
#pragma unroll
        for (int nf = 0; nf < 8; nf++) {
            int colb = (nf * 8 + (l & 3) * 2) * 2;
            __nv_bfloat162 ms0 = *(__nv_bfloat162*)(smem + ATT_MS + rw0 * 144 + colb);
            __nv_bfloat162 ms1 = *(__nv_bfloat162*)(smem + ATT_MS + (rw0 + 8) * 144 + colb);
            accS[nf][0] = fmaf(accS[nf][0], SC, __bfloat162float(ms0.x));
            accS[nf][1] = fmaf(accS[nf][1], SC, __bfloat162float(ms0.y));
            accS[nf][2] = fmaf(accS[nf][2], SC, __bfloat162float(ms1.x));
            accS[nf][3] = fmaf(accS[nf][3], SC, __bfloat162float(ms1.y));
            t0 = fmaxf(t0, fmaxf(accS[nf][0], accS[nf][1]));
            t1 = fmaxf(t1, fmaxf(accS[nf][2], accS[nf][3]));
        }
        t0 = fmaxf(t0, __shfl_xor_sync(0xffffffffu, t0, 1));
        t0 = fmaxf(t0, __shfl_xor_sync(0xffffffffu, t0, 2));
        t1 = fmaxf(t1, __shfl_xor_sync(0xffffffffu, t1, 1));
        t1 = fmaxf(t1, __shfl_xor_sync(0xffffffffu, t1, 2));

        float mn0 = fmaxf(m0r, t0), mn1 = fmaxf(m1r, t1);
        float f0 = exp2p(m0r - mn0), f1 = exp2p(m1r - mn1);
        m0r = mn0; m1r = mn1;

        float rs0 = 0.f, rs1 = 0.f;
#pragma unroll
        for (int nf = 0; nf < 8; nf++) {
            accS[nf][0] = exp2p(accS[nf][0] - m0r);
            accS[nf][1] = exp2p(accS[nf][1] - m0r);
            accS[nf][2] = exp2p(accS[nf][2] - m1r);
            accS[nf][3] = exp2p(accS[nf][3] - m1r);
            rs0 += accS[nf][0] + accS[nf][1];
            rs1 += accS[nf][2] + accS[nf][3];
            accO[nf][0] *= f0; accO[nf][1] *= f0;
            accO[nf][2] *= f1; accO[nf][3] *= f1;
        }
        rs0 += __shfl_xor_sync(0xffffffffu, rs0, 1);
        rs0 += __shfl_xor_sync(0xffffffffu, rs0, 2);
        rs1 += __shfl_xor_sync(0xffffffffu, rs1, 1);
        rs1 += __shfl_xor_sync(0xffffffffu, rs1, 2);
        l0r = l0r * f0 + rs0;
        l1r = l1r * f1 + rs1;

        // --- O += P @ V (3-pass split; P from registers, V via ldmatrix.trans) ---
#pragma unroll
        for (int kf = 0; kf < 4; kf++) {
            const float* pA = accS[2 * kf];
            const float* pB = accS[2 * kf + 1];
            float ev[8] = {pA[0], pA[1], pA[2], pA[3], pB[0], pB[1], pB[2], pB[3]};
            uint32_t ah[4], al[4];
#pragma unroll
            for (int i = 0; i < 4; i++) {
                float x = ev[2 * i], y = ev[2 * i + 1];
                __nv_bfloat16 xh = __float2bfloat16_rn(x);
                __nv_bfloat16 yh = __float2bfloat16_rn(y);
                ah[i] = pack_bf16(x, y);
                al[i] = pack_bf16(x - __bfloat162float(xh),
                                  y - __bfloat162float(yh));
            }
            int rowv = kf * 16 + (l & 15);
#pragma unroll
            for (int g = 0; g < 4; g++) {
                uint32_t vh[4], vl[4];
                int chv = g * 2 + (l >> 4);
                uint32_t off = (uint32_t)(rowv * 128 + ((chv ^ (rowv & 7)) * 16));
                ldsm_x4_t(vh, sb + ATT_VH + off);
                ldsm_x4_t(vl, sb + ATT_VL + off);
                mma_bf16(accO[2 * g],     ah, vh);
                mma_bf16(accO[2 * g],     ah, vl);
                mma_bf16(accO[2 * g],     al, vh);
                mma_bf16(accO[2 * g + 1], ah, vh + 2);
                mma_bf16(accO[2 * g + 1], ah, vl + 2);
                mma_bf16(accO[2 * g + 1], al, vh + 2);
            }
        }
        __syncthreads();
    }

    // --- finalize & write Z[b][q][h*64+d] ---
    float inv0 = 1.f / l0r, inv1 = 1.f / l1r;
    int qg0 = q0 + w * 16 + gr;
#pragma unroll
    for (int nf = 0; nf < 8; nf++) {
        int d = nf * 8 + (l & 3) * 2;
        float2 v0 = make_float2(accO[nf][0] * inv0, accO[nf][1] * inv0);
        float2 v1 = make_float2(accO[nf][2] * inv1, accO[nf][3] * inv1);
        *(float2*)&Z[((size_t)(b * Lc + qg0)) * Cc + h * 64 + d] = v0;
        *(float2*)&Z[((size_t)(b * Lc + qg0 + 8)) * Cc + h * 64 + d] = v1;
    }
}

// ============================================================================
// Launcher
// ============================================================================
extern "C" void kernel_launch(void* const* d_in, const int* in_sizes, int n_in,
                              void* d_out, int out_size)
{
    const float* query = (const float*)d_in[0];
    const float* key_  = (const float*)d_in[1];
    const float* value = (const float*)d_in[2];
    const int*   mask  = (const int*)  d_in[3];
    const float* WQ = (const float*)d_in[4];
    const float* bQ = (const float*)d_in[5];
    const float* WK = (const float*)d_in[6];
    const float* bK = (const float*)d_in[7];
    const float* WV = (const float*)d_in[8];
    const float* bV = (const float*)d_in[9];
    const float* WO = (const float*)d_in[10];
    const float* bO = (const float*)d_in[11];
    float* out = (float*)d_out;

    void *pQ, *pK, *pV, *pZ, *pM;
    cudaGetSymbolAddress(&pQ, g_Qh);
    cudaGetSymbolAddress(&pK, g_Kh);
    cudaGetSymbolAddress(&pV, g_Vh);
    cudaGetSymbolAddress(&pZ, g_Z);
    cudaGetSymbolAddress(&pM, g_Mb);
    void *wqh, *wql, *wkh, *wkl, *wvh, *wvl, *woh, *wol;
    cudaGetSymbolAddress(&wqh, g_WtQ_h); cudaGetSymbolAddress(&wql, g_WtQ_l);
    cudaGetSymbolAddress(&wkh, g_WtK_h); cudaGetSymbolAddress(&wkl, g_WtK_l);
    cudaGetSymbolAddress(&wvh, g_WtV_h); cudaGetSymbolAddress(&wvl, g_WtV_l);
    cudaGetSymbolAddress(&woh, g_WtO_h); cudaGetSymbolAddress(&wol, g_WtO_l);

    cudaFuncSetAttribute(attn_mma_kernel,
                         cudaFuncAttributeMaxDynamicSharedMemorySize, ATT_SMEM);
    cudaFuncSetAttribute(gemm_mma_kernel<0>,
                         cudaFuncAttributeMaxDynamicSharedMemorySize, G_SMEM_TOTAL);
    cudaFuncSetAttribute(gemm_mma_kernel<1>,
                         cudaFuncAttributeMaxDynamicSharedMemorySize, G_SMEM_TOTAL);

    // Prep: mask bias + weight transpose/split
    maskprep_kernel<<<(Bc * Lc * Lc) / (256 * 4), 256>>>(mask, (__nv_bfloat16*)pM);
    dim3 wgrid(32, 32), wblk(32, 8);
    wsplit_kernel<<<wgrid, wblk>>>(WQ, (__nv_bfloat16*)wqh, (__nv_bfloat16*)wql);
    wsplit_kernel<<<wgrid, wblk>>>(WK, (__nv_bfloat16*)wkh, (__nv_bfloat16*)wkl);
    wsplit_kernel<<<wgrid, wblk>>>(WV, (__nv_bfloat16*)wvh, (__nv_bfloat16*)wvl);
    wsplit_kernel<<<wgrid, wblk>>>(WO, (__nv_bfloat16*)woh, (__nv_bfloat16*)wol);

    dim3 ggrid(Cc / 128, Mc / 128);   // (8, 32)
    gemm_mma_kernel<1><<<ggrid, 256, G_SMEM_TOTAL>>>(
        query, (const __nv_bfloat16*)wqh, (const __nv_bfloat16*)wql, bQ, (float*)pQ);
    gemm_mma_kernel<1><<<ggrid, 256, G_SMEM_TOTAL>>>(
        key_,  (const __nv_bfloat16*)wkh, (const __nv_bfloat16*)wkl, bK, (float*)pK);
    gemm_mma_kernel<1><<<ggrid, 256, G_SMEM_TOTAL>>>(
        value, (const __nv_bfloat16*)wvh, (const __nv_bfloat16*)wvl, bV, (float*)pV);

    dim3 attn_grid(Lc / 128, Bc * Hc);   // (16, 32)
    attn_mma_kernel<<<attn_grid, 256, ATT_SMEM>>>(
        (const float*)pQ, (const float*)pK, (const float*)pV,
        (const __nv_bfloat16*)pM, (float*)pZ);

    gemm_mma_kernel<0><<<ggrid, 256, G_SMEM_TOTAL>>>(
        (const float*)pZ, (const __nv_bfloat16*)woh, (const __nv_bfloat16*)wol, bO, out);
}

// round 6
// speedup vs baseline: 2.7427x; 1.2749x over previous
#include <cuda_runtime.h>
#include <cuda_bf16.h>
#include <math.h>
#include <stdint.h>

// Problem constants
#define Bc 2
#define Lc 2048
#define Cc 1024
#define Hc 16
#define Dc 64
#define Mc (Bc*Lc)

// Scratch (device globals: allocation-free rule)
__device__ __nv_bfloat16 g_Xq_h[Mc*Cc], g_Xq_l[Mc*Cc];   // split inputs
__device__ __nv_bfloat16 g_Xk_h[Mc*Cc], g_Xk_l[Mc*Cc];
__device__ __nv_bfloat16 g_Xv_h[Mc*Cc], g_Xv_l[Mc*Cc];
__device__ __nv_bfloat16 g_Qb_h[Bc*Hc*Lc*Dc], g_Qb_l[Bc*Hc*Lc*Dc];
__device__ __nv_bfloat16 g_Kb_h[Bc*Hc*Lc*Dc], g_Kb_l[Bc*Hc*Lc*Dc];
__device__ __nv_bfloat16 g_Vb_h[Bc*Hc*Lc*Dc], g_Vb_l[Bc*Hc*Lc*Dc];
__device__ __nv_bfloat16 g_Zh[Bc*Lc*Cc], g_Zl[Bc*Lc*Cc];
__device__ __nv_bfloat16 g_Mb[Bc*Lc*Lc];                 // mask bias bf16

// Pre-transposed, hi/lo-split weights: [N][K] bf16
__device__ __nv_bfloat16 g_WtQ_h[Cc*Cc], g_WtQ_l[Cc*Cc];
__device__ __nv_bfloat16 g_WtK_h[Cc*Cc], g_WtK_l[Cc*Cc];
__device__ __nv_bfloat16 g_WtV_h[Cc*Cc], g_WtV_l[Cc*Cc];
__device__ __nv_bfloat16 g_WtO_h[Cc*Cc], g_WtO_l[Cc*Cc];

// ============================================================================
// Helpers
// ============================================================================
__device__ __forceinline__ uint32_t smem_u32(const void* p) {
    uint32_t a;
    asm("{ .reg .u64 t; cvta.to.shared.u64 t, %1; cvt.u32.u64 %0, t; }"
        : "=r"(a) : "l"(p));
    return a;
}
#define SWZ128(off) ((off) ^ (((off) >> 3) & 0x70))

#define CP16(dst, src) \
    asm volatile("cp.async.cg.shared.global [%0], [%1], 16;" \
                 :: "r"(dst), "l"(src) : "memory")
#define CP_COMMIT() asm volatile("cp.async.commit_group;" ::: "memory")
#define CP_WAIT1()  asm volatile("cp.async.wait_group 1;" ::: "memory")
#define CP_WAIT0()  asm volatile("cp.async.wait_group 0;" ::: "memory")

__device__ __forceinline__ void ldsm_x4(uint32_t* r, uint32_t addr) {
    asm volatile("ldmatrix.sync.aligned.m8n8.x4.shared.b16 {%0,%1,%2,%3}, [%4];"
                 : "=r"(r[0]), "=r"(r[1]), "=r"(r[2]), "=r"(r[3]) : "r"(addr));
}
__device__ __forceinline__ void ldsm_x4_t(uint32_t* r, uint32_t addr) {
    asm volatile("ldmatrix.sync.aligned.m8n8.x4.trans.shared.b16 {%0,%1,%2,%3}, [%4];"
                 : "=r"(r[0]), "=r"(r[1]), "=r"(r[2]), "=r"(r[3]) : "r"(addr));
}
__device__ __forceinline__ void mma_bf16(float* c, const uint32_t* a,
                                         const uint32_t* b) {
    asm volatile(
        "mma.sync.aligned.m16n8k16.row.col.f32.bf16.bf16.f32 "
        "{%0,%1,%2,%3}, {%4,%5,%6,%7}, {%8,%9}, {%0,%1,%2,%3};"
        : "+f"(c[0]), "+f"(c[1]), "+f"(c[2]), "+f"(c[3])
        : "r"(a[0]), "r"(a[1]), "r"(a[2]), "r"(a[3]), "r"(b[0]), "r"(b[1]));
}
__device__ __forceinline__ uint32_t pack_bf16(float x, float y) {
    __nv_bfloat162 v = __floats2bfloat162_rn(x, y);
    return *(uint32_t*)&v;
}

// ============================================================================
// Prep kernels
// ============================================================================
// fp32 [M,K] -> bf16 hi/lo, same layout.
__global__ void xsplit_kernel(const float* __restrict__ X,
                              __nv_bfloat16* __restrict__ Xh,
                              __nv_bfloat16* __restrict__ Xl)
{
    size_t i = ((size_t)blockIdx.x * 256 + threadIdx.x) * 8;
    const float4* src = (const float4*)&X[i];
    float4 x0 = src[0], x1 = src[1];
    float xs[8] = {x0.x, x0.y, x0.z, x0.w, x1.x, x1.y, x1.z, x1.w};
    __nv_bfloat16 hh[8], ll[8];
#pragma unroll
    for (int e = 0; e < 8; e++) {
        hh[e] = __float2bfloat16_rn(xs[e]);
        ll[e] = __float2bfloat16_rn(xs[e] - __bfloat162float(hh[e]));
    }
    *(uint4*)&Xh[i] = *(uint4*)hh;
    *(uint4*)&Xl[i] = *(uint4*)ll;
}

// W[k][n] fp32 -> Th/Tl[n][k] bf16 (transpose + split)
__global__ void wsplit_kernel(const float* __restrict__ W,
                              __nv_bfloat16* __restrict__ Th,
                              __nv_bfloat16* __restrict__ Tl)
{
    __shared__ float tile[32][33];
    int n0 = blockIdx.x * 32, k0 = blockIdx.y * 32;
    int tx = threadIdx.x, ty = threadIdx.y;
#pragma unroll
    for (int i = 0; i < 32; i += 8)
        tile[ty + i][tx] = W[(size_t)(k0 + ty + i) * Cc + n0 + tx];
    __syncthreads();
#pragma unroll
    for (int i = 0; i < 32; i += 8) {
        float x = tile[tx][ty + i];
        __nv_bfloat16 h = __float2bfloat16_rn(x);
        __nv_bfloat16 l = __float2bfloat16_rn(x - __bfloat162float(h));
        size_t idx = (size_t)(n0 + ty + i) * Cc + k0 + tx;
        Th[idx] = h; Tl[idx] = l;
    }
}

// mask int -> bf16 additive bias (log2 domain): (m-1)*2e9
__global__ void maskprep_kernel(const int* __restrict__ m,
                                __nv_bfloat16* __restrict__ out)
{
    int i = (blockIdx.x * 256 + threadIdx.x) * 4;
    int4 v = *(const int4*)&m[i];
    __nv_bfloat162 a, b2;
    a.x  = __float2bfloat16_rn((float)(v.x - 1) * 2.0e9f);
    a.y  = __float2bfloat16_rn((float)(v.y - 1) * 2.0e9f);
    b2.x = __float2bfloat16_rn((float)(v.z - 1) * 2.0e9f);
    b2.y = __float2bfloat16_rn((float)(v.w - 1) * 2.0e9f);
    uint2 o; o.x = *(uint32_t*)&a; o.y = *(uint32_t*)&b2;
    *(uint2*)&out[i] = o;
}

// ============================================================================
// HMMA GEMM v2: Y = A @ B^T + bias.  A = Ah+Al bf16 [M,K]; B = Bh+Bl bf16 [N,K].
// cp.async double-buffered staging, 3-pass hi/lo MMA, tile 128x128, BK=64.
// SPLITHEADS=1: write bf16 hi/lo to Yh/Yl in [B,H,L,D].  =0: fp32 to Y [M,N].
// ============================================================================
#define G_BUFSZ 65536
#define G_SMEM_TOTAL (2*G_BUFSZ)

template<int SPLITHEADS>
__global__ void __launch_bounds__(256, 1)
gemm_mma_kernel(const __nv_bfloat16* __restrict__ Ah,
                const __nv_bfloat16* __restrict__ Al,
                const __nv_bfloat16* __restrict__ Bh,
                const __nv_bfloat16* __restrict__ Bl,
                const float* __restrict__ bias,
                float* __restrict__ Y,
                __nv_bfloat16* __restrict__ Yh, __nv_bfloat16* __restrict__ Yl)
{
    extern __shared__ char smem[];
    const uint32_t sb = smem_u32(smem);

    const int t     = threadIdx.x;
    const int wid   = t >> 5;
    const int lane  = t & 31;
    const int warpM = wid & 3;
    const int warpN = wid >> 2;
    const int n0    = blockIdx.x * 128;
    const int m0    = blockIdx.y * 128;

    const __nv_bfloat16* srcs[4] = {Ah, Al, Bh, Bl};

    auto stage = [&](int s) {
        const int k0 = s * 64;
        const uint32_t bufb = sb + (s & 1) * G_BUFSZ;
#pragma unroll
        for (int u = 0; u < 16; u++) {
            int seg = t + u * 256;
            int arr = seg >> 10;
            int s2  = seg & 1023;
            int r   = s2 >> 3, c = s2 & 7;
            int rowg = (arr < 2 ? m0 : n0) + r;
            const __nv_bfloat16* g = srcs[arr] + (size_t)rowg * 1024 + k0 + c * 8;
            uint32_t dst = bufb + arr * 16384 + SWZ128((uint32_t)(r * 128 + c * 16));
            CP16(dst, g);
        }
        CP_COMMIT();
    };

    float acc[2][8][4];
#pragma unroll
    for (int mf = 0; mf < 2; mf++)
#pragma unroll
        for (int nf = 0; nf < 8; nf++)
#pragma unroll
            for (int e = 0; e < 4; e++) acc[mf][nf][e] = 0.f;

    const int mat   = lane >> 3;
    const int r8    = lane & 7;
    const int aRow0 = warpM * 32 + (mat & 1) * 8 + r8;
    const int aKh   = mat >> 1;
    const int bRow0 = warpN * 64 + (mat >> 1) * 8 + r8;
    const int bKh   = mat & 1;

    stage(0);

    for (int s = 0; s < 16; s++) {
        if (s + 1 < 16) { stage(s + 1); CP_WAIT1(); }
        else            { CP_WAIT0(); }
        __syncthreads();

        const uint32_t AH = sb + (s & 1) * G_BUFSZ;
        const uint32_t AL = AH + 16384, BH = AH + 32768, BL = AH + 49152;

#pragma unroll
        for (int ks = 0; ks < 4; ks++) {
            uint32_t aH[2][4], aL[2][4];
#pragma unroll
            for (int mf = 0; mf < 2; mf++) {
                int row = aRow0 + mf * 16;
                uint32_t off = (uint32_t)(row * 128 +
                               (((2 * ks + aKh) ^ (row & 7)) * 16));
                ldsm_x4(aH[mf], AH + off);
                ldsm_x4(aL[mf], AL + off);
            }
            uint32_t bHf[4][4], bLf[4][4];
#pragma unroll
            for (int g = 0; g < 4; g++) {
                int row = bRow0 + g * 16;
                uint32_t off = (uint32_t)(row * 128 +
                               (((2 * ks + bKh) ^ (row & 7)) * 16));
                ldsm_x4(bHf[g], BH + off);
                ldsm_x4(bLf[g], BL + off);
            }
#pragma unroll
            for (int mf = 0; mf < 2; mf++)
#pragma unroll
                for (int nf = 0; nf < 8; nf++) {
                    const uint32_t* bh = &bHf[nf >> 1][(nf & 1) * 2];
                    const uint32_t* bl = &bLf[nf >> 1][(nf & 1) * 2];
                    mma_bf16(acc[mf][nf], aH[mf], bh);
                    mma_bf16(acc[mf][nf], aH[mf], bl);
                    mma_bf16(acc[mf][nf], aL[mf], bh);
                }
        }
        __syncthreads();
    }

    const int rbase = lane >> 2;
    const int cpair = (lane & 3) * 2;
#pragma unroll
    for (int nf = 0; nf < 8; nf++) {
        int n = n0 + warpN * 64 + nf * 8 + cpair;
        float bx = __ldg(&bias[n]), by = __ldg(&bias[n + 1]);
#pragma unroll
        for (int mf = 0; mf < 2; mf++) {
            float* a = acc[mf][nf];
            int m = m0 + warpM * 32 + mf * 16 + rbase;
#pragma unroll
            for (int half = 0; half < 2; half++) {
                int mm = m + half * 8;
                float vx = a[half * 2 + 0] + bx, vy = a[half * 2 + 1] + by;
                if (SPLITHEADS) {
                    int b = mm >> 11, l = mm & 2047;
                    int h = n >> 6,  d = n & 63;
                    size_t idx = (((size_t)(b * Hc + h)) * Lc + l) * Dc + d;
                    __nv_bfloat162 hv = __floats2bfloat162_rn(vx, vy);
                    __nv_bfloat162 lv = __floats2bfloat162_rn(
                        vx - __bfloat162float(hv.x), vy - __bfloat162float(hv.y));
                    *(uint32_t*)&Yh[idx] = *(uint32_t*)&hv;
                    *(uint32_t*)&Yl[idx] = *(uint32_t*)&lv;
                } else {
                    *(float2*)&Y[(size_t)mm * 1024 + n] = make_float2(vx, vy);
                }
            }
        }
    }
}

// ============================================================================
// Fast 2^y for y <= 0 (FMA-only)
// ============================================================================
__device__ __forceinline__ float exp2p(float y)
{
    y = fmaxf(y, -126.f);
    float fl = floorf(y);
    float f  = y - fl;
    int   e  = (int)fl;
    float p  = 1.5407e-4f;
    p = fmaf(p, f, 0.0013333558f);
    p = fmaf(p, f, 0.0096181291f);
    p = fmaf(p, f, 0.0555041087f);
    p = fmaf(p, f, 0.2402265070f);
    p = fmaf(p, f, 0.6931471806f);
    p = fmaf(p, f, 1.0f);
    return p * __int_as_float((e + 127) << 23);
}

// ============================================================================
// HMMA flash attention v2: inputs pre-split bf16; cp.async double-buffered.
// Block = 128 q rows, 8 warps; K/V in 64-key tiles; P in registers.
// Output Z written as bf16 hi/lo (feeds WO GEMM directly).
// ============================================================================
#define ATT_QH 0
#define ATT_QL 16384
#define ATT_B0 32768           // per buffer: KH+0, KL+8192, VH+16384, VL+24576
#define ATT_KVBUF 32768
#define ATT_MS0 98304          // bf16 [128][72] rows (144B), per buffer 18432
#define ATT_MSBUF 18432
#define ATT_SMEM 135168

__global__ void __launch_bounds__(256, 1)
attn_mma_kernel(const __nv_bfloat16* __restrict__ Qh, const __nv_bfloat16* __restrict__ Ql,
                const __nv_bfloat16* __restrict__ Kh, const __nv_bfloat16* __restrict__ Kl,
                const __nv_bfloat16* __restrict__ Vh, const __nv_bfloat16* __restrict__ Vl,
                const __nv_bfloat16* __restrict__ Mb,
                __nv_bfloat16* __restrict__ Zh, __nv_bfloat16* __restrict__ Zl)
{
    extern __shared__ char smem[];
    const uint32_t sb = smem_u32(smem);
    const int t  = threadIdx.x;
    const int w  = t >> 5;
    const int l  = t & 31;
    const int bh = blockIdx.y;
    const int b  = bh >> 4;
    const int h  = bh & 15;
    const int q0 = blockIdx.x * 128;

    const __nv_bfloat16* Qbh = Qh + (size_t)bh * Lc * Dc;
    const __nv_bfloat16* Qbl = Ql + (size_t)bh * Lc * Dc;
    const __nv_bfloat16* Kbh = Kh + (size_t)bh * Lc * Dc;
    const __nv_bfloat16* Kbl = Kl + (size_t)bh * Lc * Dc;
    const __nv_bfloat16* Vbh = Vh + (size_t)bh * Lc * Dc;
    const __nv_bfloat16* Vbl = Vl + (size_t)bh * Lc * Dc;
    const __nv_bfloat16* Mbb = Mb + ((size_t)b * Lc + q0) * Lc;

    const float SC = 0.125f * 1.4426950408889634f;
    const int mat = l >> 3;
    const int r8  = l & 7;
    const int gr  = l >> 2;

    const __nv_bfloat16* kvsrc[4] = {Kbh, Kbl, Vbh, Vbl};

    auto stage = [&](int s) {
        const int kt = s * 64;
        const uint32_t kvb = sb + ATT_B0 + (s & 1) * ATT_KVBUF;
        const uint32_t msb = sb + ATT_MS0 + (s & 1) * ATT_MSBUF;
        // K/V: 4 arrays x 64 rows x 8 chunks = 2048 -> 8/thread
#pragma unroll
        for (int u = 0; u < 8; u++) {
            int seg = t + u * 256;
            int arr = seg >> 9;
            int s2  = seg & 511;
            int r   = s2 >> 3, c = s2 & 7;
            const __nv_bfloat16* g = kvsrc[arr] + (size_t)(kt + r) * Dc + c * 8;
            uint32_t dst = kvb + arr * 8192 + SWZ128((uint32_t)(r * 128 + c * 16));
            CP16(dst, g);
        }
        // mask: 128 rows x 8 chunks = 1024 -> 4/thread
#pragma unroll
        for (int u = 0; u < 4; u++) {
            int seg = t + u * 256;
            int r = seg >> 3, c = seg & 7;
            const __nv_bfloat16* g = Mbb + (size_t)r * Lc + kt + c * 8;
            CP16(msb + r * 144 + c * 16, g);
        }
        CP_COMMIT();
    };

    // Prologue: Q hi/lo (2 arrays x 128 rows x 8 chunks = 2048 -> 8/thread) + tile 0
#pragma unroll
    for (int u = 0; u < 8; u++) {
        int seg = t + u * 256;
        int arr = seg >> 10;
        int s2  = seg & 1023;
        int r   = s2 >> 3, c = s2 & 7;
        const __nv_bfloat16* g = (arr ? Qbl : Qbh) + (size_t)(q0 + r) * Dc + c * 8;
        uint32_t dst = sb + (arr ? ATT_QL : ATT_QH) + SWZ128((uint32_t)(r * 128 + c * 16));
        CP16(dst, g);
    }
    stage(0);

    float accO[8][4];
#pragma unroll
    for (int nf = 0; nf < 8; nf++)
#pragma unroll
        for (int e = 0; e < 4; e++) accO[nf][e] = 0.f;
    float m0r = -3.0e38f, m1r = -3.0e38f, l0r = 0.f, l1r = 0.f;

    for (int s = 0; s < 32; s++) {
        if (s + 1 < 32) { stage(s + 1); CP_WAIT1(); }
        else            { CP_WAIT0(); }
        __syncthreads();

        const uint32_t KHb = sb + ATT_B0 + (s & 1) * ATT_KVBUF;
        const uint32_t KLb = KHb + 8192, VHb = KHb + 16384, VLb = KHb + 24576;
        const uint32_t MSb = sb + ATT_MS0 + (s & 1) * ATT_MSBUF;

        // --- S = Q K^T (3-pass split) ---
        float accS[8][4];
#pragma unroll
        for (int nf = 0; nf < 8; nf++)
#pragma unroll
            for (int e = 0; e < 4; e++) accS[nf][e] = 0.f;

#pragma unroll
        for (int kf = 0; kf < 4; kf++) {
            uint32_t qh[4], ql[4];
            {
                int row = w * 16 + (mat & 1) * 8 + r8;
                int chk = kf * 2 + (mat >> 1);
                uint32_t off = (uint32_t)(row * 128 + ((chk ^ (row & 7)) * 16));
                ldsm_x4(qh, sb + ATT_QH + off);
                ldsm_x4(ql, sb + ATT_QL + off);
            }
#pragma unroll
            for (int g = 0; g < 4; g++) {
                uint32_t kh[4], kl[4];
                int row = g * 16 + (mat >> 1) * 8 + r8;
                int chk = kf * 2 + (mat & 1);
                uint32_t off = (uint32_t)(row * 128 + ((chk ^ (row & 7)) * 16));
                ldsm_x4(kh, KHb + off);
                ldsm_x4(kl, KLb + off);
                mma_bf16(accS[2 * g],     qh, kh);
                mma_bf16(accS[2 * g],     qh, kl);
                mma_bf16(accS[2 * g],     ql, kh);
                mma_bf16(accS[2 * g + 1], qh, kh + 2);
                mma_bf16(accS[2 * g + 1], qh, kl + 2);
                mma_bf16(accS[2 * g + 1], ql, kh + 2);
            }
        }

        // --- softmax (fp32, log2 domain, registers) ---
        const int rw0 = w * 16 + gr;
        float t0 = -3.0e38f, t1 = -3.0e38f;
#pragma unroll
        for (int nf = 0; nf < 8; nf++) {
            int colb = (nf * 8 + (l & 3) * 2) * 2;
            __nv_bfloat162 ms0 = *(__nv_bfloat162*)(smem + (MSb - sb) + rw0 * 144 + colb);
            __nv_bfloat162 ms1 = *(__nv_bfloat162*)(smem + (MSb - sb) + (rw0 + 8) * 144 + colb);
            accS[nf][0] = fmaf(accS[nf][0], SC, __bfloat162float(ms0.x));
            accS[nf][1] = fmaf(accS[nf][1], SC, __bfloat162float(ms0.y));
            accS[nf][2] = fmaf(accS[nf][2], SC, __bfloat162float(ms1.x));
            accS[nf][3] = fmaf(accS[nf][3], SC, __bfloat162float(ms1.y));
            t0 = fmaxf(t0, fmaxf(accS[nf][0], accS[nf][1]));
            t1 = fmaxf(t1, fmaxf(accS[nf][2], accS[nf][3]));
        }
        t0 = fmaxf(t0, __shfl_xor_sync(0xffffffffu, t0, 1));
        t0 = fmaxf(t0, __shfl_xor_sync(0xffffffffu, t0, 2));
        t1 = fmaxf(t1, __shfl_xor_sync(0xffffffffu, t1, 1));
        t1 = fmaxf(t1, __shfl_xor_sync(0xffffffffu, t1, 2));

        float mn0 = fmaxf(m0r, t0), mn1 = fmaxf(m1r, t1);
        float f0 = exp2p(m0r - mn0), f1 = exp2p(m1r - mn1);
        m0r = mn0; m1r = mn1;

        float rs0 = 0.f, rs1 = 0.f;
#pragma unroll
        for (int nf = 0; nf < 8; nf++) {
            accS[nf][0] = exp2p(accS[nf][0] - m0r);
            accS[nf][1] = exp2p(accS[nf][1] - m0r);
            accS[nf][2] = exp2p(accS[nf][2] - m1r);
            accS[nf][3] = exp2p(accS[nf][3] - m1r);
            rs0 += accS[nf][0] + accS[nf][1];
            rs1 += accS[nf][2] + accS[nf][3];
            accO[nf][0] *= f0; accO[nf][1] *= f0;
            accO[nf][2] *= f1; accO[nf][3] *= f1;
        }
        rs0 += __shfl_xor_sync(0xffffffffu, rs0, 1);
        rs0 += __shfl_xor_sync(0xffffffffu, rs0, 2);
        rs1 += __shfl_xor_sync(0xffffffffu, rs1, 1);
        rs1 += __shfl_xor_sync(0xffffffffu, rs1, 2);
        l0r = l0r * f0 + rs0;
        l1r = l1r * f1 + rs1;

        // --- O += P @ V (3-pass; P hi/lo from registers, V via ldmatrix.trans) ---
#pragma unroll
        for (int kf = 0; kf < 4; kf++) {
            const float* pA = accS[2 * kf];
            const float* pB = accS[2 * kf + 1];
            float ev[8] = {pA[0], pA[1], pA[2], pA[3], pB[0], pB[1], pB[2], pB[3]};
            uint32_t ah[4], al[4];
#pragma unroll
            for (int i = 0; i < 4; i++) {
                float x = ev[2 * i], y = ev[2 * i + 1];
                __nv_bfloat16 xh = __float2bfloat16_rn(x);
                __nv_bfloat16 yh = __float2bfloat16_rn(y);
                ah[i] = pack_bf16(x, y);
                al[i] = pack_bf16(x - __bfloat162float(xh),
                                  y - __bfloat162float(yh));
            }
            int rowv = kf * 16 + (l & 15);
#pragma unroll
            for (int g = 0; g < 4; g++) {
                uint32_t vh[4], vl[4];
                int chv = g * 2 + (l >> 4);
                uint32_t off = (uint32_t)(rowv * 128 + ((chv ^ (rowv & 7)) * 16));
                ldsm_x4_t(vh, VHb + off);
                ldsm_x4_t(vl, VLb + off);
                mma_bf16(accO[2 * g],     ah, vh);
                mma_bf16(accO[2 * g],     ah, vl);
                mma_bf16(accO[2 * g],     al, vh);
                mma_bf16(accO[2 * g + 1], ah, vh + 2);
                mma_bf16(accO[2 * g + 1], ah, vl + 2);
                mma_bf16(accO[2 * g + 1], al, vh + 2);
            }
        }
        __syncthreads();
    }

    // --- finalize: divide, split hi/lo, write Zh/Zl [b][q][h*64+d] ---
    float inv0 = 1.f / l0r, inv1 = 1.f / l1r;
    int qg0 = q0 + w * 16 + gr;
#pragma unroll
    for (int nf = 0; nf < 8; nf++) {
        int d = nf * 8 + (l & 3) * 2;
        float x0 = accO[nf][0] * inv0, y0 = accO[nf][1] * inv0;
        float x1 = accO[nf][2] * inv1, y1 = accO[nf][3] * inv1;
        size_t i0 = ((size_t)(b * Lc + qg0)) * Cc + h * 64 + d;
        size_t i1 = ((size_t)(b * Lc + qg0 + 8)) * Cc + h * 64 + d;
        __nv_bfloat162 h0 = __floats2bfloat162_rn(x0, y0);
        __nv_bfloat162 l0 = __floats2bfloat162_rn(
            x0 - __bfloat162float(h0.x), y0 - __bfloat162float(h0.y));
        __nv_bfloat162 h1 = __floats2bfloat162_rn(x1, y1);
        __nv_bfloat162 l1 = __floats2bfloat162_rn(
            x1 - __bfloat162float(h1.x), y1 - __bfloat162float(h1.y));
        *(uint32_t*)&Zh[i0] = *(uint32_t*)&h0;
        *(uint32_t*)&Zl[i0] = *(uint32_t*)&l0;
        *(uint32_t*)&Zh[i1] = *(uint32_t*)&h1;
        *(uint32_t*)&Zl[i1] = *(uint32_t*)&l1;
    }
}

// ============================================================================
// Launcher
// ============================================================================
extern "C" void kernel_launch(void* const* d_in, const int* in_sizes, int n_in,
                              void* d_out, int out_size)
{
    const float* query = (const float*)d_in[0];
    const float* key_  = (const float*)d_in[1];
    const float* value = (const float*)d_in[2];
    const int*   mask  = (const int*)  d_in[3];
    const float* WQ = (const float*)d_in[4];
    const float* bQ = (const float*)d_in[5];
    const float* WK = (const float*)d_in[6];
    const float* bK = (const float*)d_in[7];
    const float* WV = (const float*)d_in[8];
    const float* bV = (const float*)d_in[9];
    const float* WO = (const float*)d_in[10];
    const float* bO = (const float*)d_in[11];
    float* out = (float*)d_out;

    void *xqh, *xql, *xkh, *xkl, *xvh, *xvl;
    cudaGetSymbolAddress(&xqh, g_Xq_h); cudaGetSymbolAddress(&xql, g_Xq_l);
    cudaGetSymbolAddress(&xkh, g_Xk_h); cudaGetSymbolAddress(&xkl, g_Xk_l);
    cudaGetSymbolAddress(&xvh, g_Xv_h); cudaGetSymbolAddress(&xvl, g_Xv_l);
    void *qbh, *qbl, *kbh, *kbl, *vbh, *vbl, *zh, *zl, *pM;
    cudaGetSymbolAddress(&qbh, g_Qb_h); cudaGetSymbolAddress(&qbl, g_Qb_l);
    cudaGetSymbolAddress(&kbh, g_Kb_h); cudaGetSymbolAddress(&kbl, g_Kb_l);
    cudaGetSymbolAddress(&vbh, g_Vb_h); cudaGetSymbolAddress(&vbl, g_Vb_l);
    cudaGetSymbolAddress(&zh, g_Zh);    cudaGetSymbolAddress(&zl, g_Zl);
    cudaGetSymbolAddress(&pM, g_Mb);
    void *wqh, *wql, *wkh, *wkl, *wvh, *wvl, *woh, *wol;
    cudaGetSymbolAddress(&wqh, g_WtQ_h); cudaGetSymbolAddress(&wql, g_WtQ_l);
    cudaGetSymbolAddress(&wkh, g_WtK_h); cudaGetSymbolAddress(&wkl, g_WtK_l);
    cudaGetSymbolAddress(&wvh, g_WtV_h); cudaGetSymbolAddress(&wvl, g_WtV_l);
    cudaGetSymbolAddress(&woh, g_WtO_h); cudaGetSymbolAddress(&wol, g_WtO_l);

    cudaFuncSetAttribute(attn_mma_kernel,
                         cudaFuncAttributeMaxDynamicSharedMemorySize, ATT_SMEM);
    cudaFuncSetAttribute(gemm_mma_kernel<0>,
                         cudaFuncAttributeMaxDynamicSharedMemorySize, G_SMEM_TOTAL);
    cudaFuncSetAttribute(gemm_mma_kernel<1>,
                         cudaFuncAttributeMaxDynamicSharedMemorySize, G_SMEM_TOTAL);

    // Prep: input splits, mask bias, weight transpose/split
    const int xgrid = Mc * Cc / (256 * 8);   // 2048
    xsplit_kernel<<<xgrid, 256>>>(query, (__nv_bfloat16*)xqh, (__nv_bfloat16*)xql);
    xsplit_kernel<<<xgrid, 256>>>(key_,  (__nv_bfloat16*)xkh, (__nv_bfloat16*)xkl);
    xsplit_kernel<<<xgrid, 256>>>(value, (__nv_bfloat16*)xvh, (__nv_bfloat16*)xvl);
    maskprep_kernel<<<(Bc * Lc * Lc) / (256 * 4), 256>>>(mask, (__nv_bfloat16*)pM);
    dim3 wgrid(32, 32), wblk(32, 8);
    wsplit_kernel<<<wgrid, wblk>>>(WQ, (__nv_bfloat16*)wqh, (__nv_bfloat16*)wql);
    wsplit_kernel<<<wgrid, wblk>>>(WK, (__nv_bfloat16*)wkh, (__nv_bfloat16*)wkl);
    wsplit_kernel<<<wgrid, wblk>>>(WV, (__nv_bfloat16*)wvh, (__nv_bfloat16*)wvl);
    wsplit_kernel<<<wgrid, wblk>>>(WO, (__nv_bfloat16*)woh, (__nv_bfloat16*)wol);

    dim3 ggrid(Cc / 128, Mc / 128);   // (8, 32)
    gemm_mma_kernel<1><<<ggrid, 256, G_SMEM_TOTAL>>>(
        (const __nv_bfloat16*)xqh, (const __nv_bfloat16*)xql,
        (const __nv_bfloat16*)wqh, (const __nv_bfloat16*)wql, bQ,
        nullptr, (__nv_bfloat16*)qbh, (__nv_bfloat16*)qbl);
    gemm_mma_kernel<1><<<ggrid, 256, G_SMEM_TOTAL>>>(
        (const __nv_bfloat16*)xkh, (const __nv_bfloat16*)xkl,
        (const __nv_bfloat16*)wkh, (const __nv_bfloat16*)wkl, bK,
        nullptr, (__nv_bfloat16*)kbh, (__nv_bfloat16*)kbl);
    gemm_mma_kernel<1><<<ggrid, 256, G_SMEM_TOTAL>>>(
        (const __nv_bfloat16*)xvh, (const __nv_bfloat16*)xvl,
        (const __nv_bfloat16*)wvh, (const __nv_bfloat16*)wvl, bV,
        nullptr, (__nv_bfloat16*)vbh, (__nv_bfloat16*)vbl);

    dim3 attn_grid(Lc / 128, Bc * Hc);   // (16, 32)
    attn_mma_kernel<<<attn_grid, 256, ATT_SMEM>>>(
        (const __nv_bfloat16*)qbh, (const __nv_bfloat16*)qbl,
        (const __nv_bfloat16*)kbh, (const __nv_bfloat16*)kbl,
        (const __nv_bfloat16*)vbh, (const __nv_bfloat16*)vbl,
        (const __nv_bfloat16*)pM, (__nv_bfloat16*)zh, (__nv_bfloat16*)zl);

    gemm_mma_kernel<0><<<ggrid, 256, G_SMEM_TOTAL>>>(
        (const __nv_bfloat16*)zh, (const __nv_bfloat16*)zl,
        (const __nv_bfloat16*)woh, (const __nv_bfloat16*)wol, bO,
        out, nullptr, nullptr);
}

// round 8
// speedup vs baseline: 2.8577x; 1.0419x over previous
#include <cuda_runtime.h>
#include <cuda_bf16.h>
#include <math.h>
#include <stdint.h>

// Problem constants
#define Bc 2
#define Lc 2048
#define Cc 1024
#define Hc 16
#define Dc 64
#define Mc (Bc*Lc)

// Scratch (device globals: allocation-free rule)
__device__ __nv_bfloat16 g_Xq_h[Mc*Cc], g_Xq_l[Mc*Cc];
__device__ __nv_bfloat16 g_Xk_h[Mc*Cc], g_Xk_l[Mc*Cc];
__device__ __nv_bfloat16 g_Xv_h[Mc*Cc], g_Xv_l[Mc*Cc];
__device__ __nv_bfloat16 g_Qb_h[Bc*Hc*Lc*Dc], g_Qb_l[Bc*Hc*Lc*Dc];
__device__ __nv_bfloat16 g_Kb_h[Bc*Hc*Lc*Dc], g_Kb_l[Bc*Hc*Lc*Dc];
__device__ __nv_bfloat16 g_Vb_h[Bc*Hc*Lc*Dc], g_Vb_l[Bc*Hc*Lc*Dc];
__device__ __nv_bfloat16 g_Zh[Bc*Lc*Cc], g_Zl[Bc*Lc*Cc];
__device__ __nv_bfloat16 g_Mb[Bc*Lc*Lc];

__device__ __nv_bfloat16 g_WtQ_h[Cc*Cc], g_WtQ_l[Cc*Cc];
__device__ __nv_bfloat16 g_WtK_h[Cc*Cc], g_WtK_l[Cc*Cc];
__device__ __nv_bfloat16 g_WtV_h[Cc*Cc], g_WtV_l[Cc*Cc];
__device__ __nv_bfloat16 g_WtO_h[Cc*Cc], g_WtO_l[Cc*Cc];

// ============================================================================
// Helpers
// ============================================================================
__device__ __forceinline__ uint32_t smem_u32(const void* p) {
    uint32_t a;
    asm("{ .reg .u64 t; cvta.to.shared.u64 t, %1; cvt.u32.u64 %0, t; }"
        : "=r"(a) : "l"(p));
    return a;
}
#define SWZ128(off) ((off) ^ (((off) >> 3) & 0x70))

#define CP16(dst, src) \
    asm volatile("cp.async.cg.shared.global [%0], [%1], 16;" \
                 :: "r"(dst), "l"(src) : "memory")
#define CP_COMMIT() asm volatile("cp.async.commit_group;" ::: "memory")
#define CP_WAIT1()  asm volatile("cp.async.wait_group 1;" ::: "memory")
#define CP_WAIT0()  asm volatile("cp.async.wait_group 0;" ::: "memory")

__device__ __forceinline__ void ldsm_x4(uint32_t* r, uint32_t addr) {
    asm volatile("ldmatrix.sync.aligned.m8n8.x4.shared.b16 {%0,%1,%2,%3}, [%4];"
                 : "=r"(r[0]), "=r"(r[1]), "=r"(r[2]), "=r"(r[3]) : "r"(addr));
}
__device__ __forceinline__ void ldsm_x4_t(uint32_t* r, uint32_t addr) {
    asm volatile("ldmatrix.sync.aligned.m8n8.x4.trans.shared.b16 {%0,%1,%2,%3}, [%4];"
                 : "=r"(r[0]), "=r"(r[1]), "=r"(r[2]), "=r"(r[3]) : "r"(addr));
}
__device__ __forceinline__ void mma_bf16(float* c, const uint32_t* a,
                                         const uint32_t* b) {
    asm volatile(
        "mma.sync.aligned.m16n8k16.row.col.f32.bf16.bf16.f32 "
        "{%0,%1,%2,%3}, {%4,%5,%6,%7}, {%8,%9}, {%0,%1,%2,%3};"
        : "+f"(c[0]), "+f"(c[1]), "+f"(c[2]), "+f"(c[3])
        : "r"(a[0]), "r"(a[1]), "r"(a[2]), "r"(a[3]), "r"(b[0]), "r"(b[1]));
}
__device__ __forceinline__ uint32_t pack_bf16(float x, float y) {
    __nv_bfloat162 v = __floats2bfloat162_rn(x, y);
    return *(uint32_t*)&v;
}
// MUFU exp2 — single instruction; large-negative input -> 0
__device__ __forceinline__ float ex2f(float x) {
    float y;
    asm("ex2.approx.f32 %0, %1;" : "=f"(y) : "f"(x));
    return y;
}

// ============================================================================
// Prep kernels (fused variants)
// ============================================================================
struct XSplitBatch {
    const float* X[3];
    __nv_bfloat16 *Xh[3], *Xl[3];
};
__global__ void xsplit_kernel(XSplitBatch p)
{
    int z = blockIdx.y;
    size_t i = ((size_t)blockIdx.x * 256 + threadIdx.x) * 8;
    const float4* src = (const float4*)&p.X[z][i];
    float4 x0 = src[0], x1 = src[1];
    float xs[8] = {x0.x, x0.y, x0.z, x0.w, x1.x, x1.y, x1.z, x1.w};
    __nv_bfloat16 hh[8], ll[8];
#pragma unroll
    for (int e = 0; e < 8; e++) {
        hh[e] = __float2bfloat16_rn(xs[e]);
        ll[e] = __float2bfloat16_rn(xs[e] - __bfloat162float(hh[e]));
    }
    *(uint4*)&p.Xh[z][i] = *(uint4*)hh;
    *(uint4*)&p.Xl[z][i] = *(uint4*)ll;
}

struct WSplitBatch {
    const float* W[4];
    __nv_bfloat16 *Th[4], *Tl[4];
};
__global__ void wsplit_kernel(WSplitBatch p)
{
    __shared__ float tile[32][33];
    int z = blockIdx.z;
    int n0 = blockIdx.x * 32, k0 = blockIdx.y * 32;
    int tx = threadIdx.x, ty = threadIdx.y;
#pragma unroll
    for (int i = 0; i < 32; i += 8)
        tile[ty + i][tx] = p.W[z][(size_t)(k0 + ty + i) * Cc + n0 + tx];
    __syncthreads();
#pragma unroll
    for (int i = 0; i < 32; i += 8) {
        float x = tile[tx][ty + i];
        __nv_bfloat16 h = __float2bfloat16_rn(x);
        __nv_bfloat16 l = __float2bfloat16_rn(x - __bfloat162float(h));
        size_t idx = (size_t)(n0 + ty + i) * Cc + k0 + tx;
        p.Th[z][idx] = h; p.Tl[z][idx] = l;
    }
}

__global__ void maskprep_kernel(const int* __restrict__ m,
                                __nv_bfloat16* __restrict__ out)
{
    int i = (blockIdx.x * 256 + threadIdx.x) * 4;
    int4 v = *(const int4*)&m[i];
    __nv_bfloat162 a, b2;
    a.x  = __float2bfloat16_rn((float)(v.x - 1) * 2.0e9f);
    a.y  = __float2bfloat16_rn((float)(v.y - 1) * 2.0e9f);
    b2.x = __float2bfloat16_rn((float)(v.z - 1) * 2.0e9f);
    b2.y = __float2bfloat16_rn((float)(v.w - 1) * 2.0e9f);
    uint2 o; o.x = *(uint32_t*)&a; o.y = *(uint32_t*)&b2;
    *(uint2*)&out[i] = o;
}

// ============================================================================
// HMMA GEMM core: Y = A @ B^T + bias, 3-pass hi/lo split,
// cp.async double-buffered, tile 128x128, BK=64.
// ============================================================================
#define G_BUFSZ 65536
#define G_SMEM_TOTAL (2*G_BUFSZ)

template<int SPLITHEADS>
__device__ __forceinline__ void gemm_body(
    const __nv_bfloat16* __restrict__ Ah, const __nv_bfloat16* __restrict__ Al,
    const __nv_bfloat16* __restrict__ Bh, const __nv_bfloat16* __restrict__ Bl,
    const float* __restrict__ bias, float* __restrict__ Y,
    __nv_bfloat16* __restrict__ Yh, __nv_bfloat16* __restrict__ Yl,
    char* smem)
{
    const uint32_t sb = smem_u32(smem);
    const int t     = threadIdx.x;
    const int wid   = t >> 5;
    const int lane  = t & 31;
    const int warpM = wid & 3;
    const int warpN = wid >> 2;
    const int n0    = blockIdx.x * 128;
    const int m0    = blockIdx.y * 128;

    const __nv_bfloat16* srcs[4] = {Ah, Al, Bh, Bl};

    auto stage = [&](int s) {
        const int k0 = s * 64;
        const uint32_t bufb = sb + (s & 1) * G_BUFSZ;
#pragma unroll
        for (int u = 0; u < 16; u++) {
            int seg = t + u * 256;
            int arr = seg >> 10;
            int s2  = seg & 1023;
            int r   = s2 >> 3, c = s2 & 7;
            int rowg = (arr < 2 ? m0 : n0) + r;
            const __nv_bfloat16* g = srcs[arr] + (size_t)rowg * 1024 + k0 + c * 8;
            uint32_t dst = bufb + arr * 16384 + SWZ128((uint32_t)(r * 128 + c * 16));
            CP16(dst, g);
        }
        CP_COMMIT();
    };

    float acc[2][8][4];
#pragma unroll
    for (int mf = 0; mf < 2; mf++)
#pragma unroll
        for (int nf = 0; nf < 8; nf++)
#pragma unroll
            for (int e = 0; e < 4; e++) acc[mf][nf][e] = 0.f;

    const int mat   = lane >> 3;
    const int r8    = lane & 7;
    const int aRow0 = warpM * 32 + (mat & 1) * 8 + r8;
    const int aKh   = mat >> 1;
    const int bRow0 = warpN * 64 + (mat >> 1) * 8 + r8;
    const int bKh   = mat & 1;

    stage(0);

    for (int s = 0; s < 16; s++) {
        if (s + 1 < 16) { stage(s + 1); CP_WAIT1(); }
        else            { CP_WAIT0(); }
        __syncthreads();

        const uint32_t AH = sb + (s & 1) * G_BUFSZ;
        const uint32_t AL = AH + 16384, BH = AH + 32768, BL = AH + 49152;

#pragma unroll
        for (int ks = 0; ks < 4; ks++) {
            uint32_t aH[2][4], aL[2][4];
#pragma unroll
            for (int mf = 0; mf < 2; mf++) {
                int row = aRow0 + mf * 16;
                uint32_t off = (uint32_t)(row * 128 +
                               (((2 * ks + aKh) ^ (row & 7)) * 16));
                ldsm_x4(aH[mf], AH + off);
                ldsm_x4(aL[mf], AL + off);
            }
            uint32_t bHf[4][4], bLf[4][4];
#pragma unroll
            for (int g = 0; g < 4; g++) {
                int row = bRow0 + g * 16;
                uint32_t off = (uint32_t)(row * 128 +
                               (((2 * ks + bKh) ^ (row & 7)) * 16));
                ldsm_x4(bHf[g], BH + off);
                ldsm_x4(bLf[g], BL + off);
            }
#pragma unroll
            for (int mf = 0; mf < 2; mf++)
#pragma unroll
                for (int nf = 0; nf < 8; nf++) {
                    const uint32_t* bh = &bHf[nf >> 1][(nf & 1) * 2];
                    const uint32_t* bl = &bLf[nf >> 1][(nf & 1) * 2];
                    mma_bf16(acc[mf][nf], aH[mf], bh);
                    mma_bf16(acc[mf][nf], aH[mf], bl);
                    mma_bf16(acc[mf][nf], aL[mf], bh);
                }
        }
        __syncthreads();
    }

    const int rbase = lane >> 2;
    const int cpair = (lane & 3) * 2;
#pragma unroll
    for (int nf = 0; nf < 8; nf++) {
        int n = n0 + warpN * 64 + nf * 8 + cpair;
        float bx = __ldg(&bias[n]), by = __ldg(&bias[n + 1]);
#pragma unroll
        for (int mf = 0; mf < 2; mf++) {
            float* a = acc[mf][nf];
            int m = m0 + warpM * 32 + mf * 16 + rbase;
#pragma unroll
            for (int half = 0; half < 2; half++) {
                int mm = m + half * 8;
                float vx = a[half * 2 + 0] + bx, vy = a[half * 2 + 1] + by;
                if (SPLITHEADS) {
                    int b = mm >> 11, l = mm & 2047;
                    int h = n >> 6,  d = n & 63;
                    size_t idx = (((size_t)(b * Hc + h)) * Lc + l) * Dc + d;
                    __nv_bfloat162 hv = __floats2bfloat162_rn(vx, vy);
                    __nv_bfloat162 lv = __floats2bfloat162_rn(
                        vx - __bfloat162float(hv.x), vy - __bfloat162float(hv.y));
                    *(uint32_t*)&Yh[idx] = *(uint32_t*)&hv;
                    *(uint32_t*)&Yl[idx] = *(uint32_t*)&lv;
                } else {
                    *(float2*)&Y[(size_t)mm * 1024 + n] = make_float2(vx, vy);
                }
            }
        }
    }
}

struct GemmBatch {
    const __nv_bfloat16 *Ah[3], *Al[3], *Bh[3], *Bl[3];
    const float* bias[3];
    __nv_bfloat16 *Yh[3], *Yl[3];
};

__global__ void __launch_bounds__(256, 1) gemm_proj_kernel(GemmBatch p)
{
    extern __shared__ char smem[];
    int z = blockIdx.z;
    gemm_body<1>(p.Ah[z], p.Al[z], p.Bh[z], p.Bl[z], p.bias[z],
                 nullptr, p.Yh[z], p.Yl[z], smem);
}

__global__ void __launch_bounds__(256, 1)
gemm_out_kernel(const __nv_bfloat16* Ah, const __nv_bfloat16* Al,
                const __nv_bfloat16* Bh, const __nv_bfloat16* Bl,
                const float* bias, float* Y)
{
    extern __shared__ char smem[];
    gemm_body<0>(Ah, Al, Bh, Bl, bias, Y, nullptr, nullptr, smem);
}

// ============================================================================
// HMMA flash attention: MUFU exp, 3-pass PV (P hi/lo restored), cp.async.
// ============================================================================
#define ATT_QH 0
#define ATT_QL 16384
#define ATT_B0 32768
#define ATT_KVBUF 32768
#define ATT_MS0 98304
#define ATT_MSBUF 18432
#define ATT_SMEM 135168

__global__ void __launch_bounds__(256, 1)
attn_mma_kernel(const __nv_bfloat16* __restrict__ Qh, const __nv_bfloat16* __restrict__ Ql,
                const __nv_bfloat16* __restrict__ Kh, const __nv_bfloat16* __restrict__ Kl,
                const __nv_bfloat16* __restrict__ Vh, const __nv_bfloat16* __restrict__ Vl,
                const __nv_bfloat16* __restrict__ Mb,
                __nv_bfloat16* __restrict__ Zh, __nv_bfloat16* __restrict__ Zl)
{
    extern __shared__ char smem[];
    const uint32_t sb = smem_u32(smem);
    const int t  = threadIdx.x;
    const int w  = t >> 5;
    const int l  = t & 31;
    const int bh = blockIdx.y;
    const int b  = bh >> 4;
    const int h  = bh & 15;
    const int q0 = blockIdx.x * 128;

    const __nv_bfloat16* Qbh = Qh + (size_t)bh * Lc * Dc;
    const __nv_bfloat16* Qbl = Ql + (size_t)bh * Lc * Dc;
    const __nv_bfloat16* Kbh = Kh + (size_t)bh * Lc * Dc;
    const __nv_bfloat16* Kbl = Kl + (size_t)bh * Lc * Dc;
    const __nv_bfloat16* Vbh = Vh + (size_t)bh * Lc * Dc;
    const __nv_bfloat16* Vbl = Vl + (size_t)bh * Lc * Dc;
    const __nv_bfloat16* Mbb = Mb + ((size_t)b * Lc + q0) * Lc;

    const float SC = 0.125f * 1.4426950408889634f;
    const int mat = l >> 3;
    const int r8  = l & 7;
    const int gr  = l >> 2;

    const __nv_bfloat16* kvsrc[4] = {Kbh, Kbl, Vbh, Vbl};

    auto stage = [&](int s) {
        const int kt = s * 64;
        const uint32_t kvb = sb + ATT_B0 + (s & 1) * ATT_KVBUF;
        const uint32_t msb = sb + ATT_MS0 + (s & 1) * ATT_MSBUF;
#pragma unroll
        for (int u = 0; u < 8; u++) {
            int seg = t + u * 256;
            int arr = seg >> 9;
            int s2  = seg & 511;
            int r   = s2 >> 3, c = s2 & 7;
            const __nv_bfloat16* g = kvsrc[arr] + (size_t)(kt + r) * Dc + c * 8;
            uint32_t dst = kvb + arr * 8192 + SWZ128((uint32_t)(r * 128 + c * 16));
            CP16(dst, g);
        }
#pragma unroll
        for (int u = 0; u < 4; u++) {
            int seg = t + u * 256;
            int r = seg >> 3, c = seg & 7;
            const __nv_bfloat16* g = Mbb + (size_t)r * Lc + kt + c * 8;
            CP16(msb + r * 144 + c * 16, g);
        }
        CP_COMMIT();
    };

#pragma unroll
    for (int u = 0; u < 8; u++) {
        int seg = t + u * 256;
        int arr = seg >> 10;
        int s2  = seg & 1023;
        int r   = s2 >> 3, c = s2 & 7;
        const __nv_bfloat16* g = (arr ? Qbl : Qbh) + (size_t)(q0 + r) * Dc + c * 8;
        uint32_t dst = sb + (arr ? ATT_QL : ATT_QH) + SWZ128((uint32_t)(r * 128 + c * 16));
        CP16(dst, g);
    }
    stage(0);

    float accO[8][4];
#pragma unroll
    for (int nf = 0; nf < 8; nf++)
#pragma unroll
        for (int e = 0; e < 4; e++) accO[nf][e] = 0.f;
    float m0r = -3.0e38f, m1r = -3.0e38f, l0r = 0.f, l1r = 0.f;

    for (int s = 0; s < 32; s++) {
        if (s + 1 < 32) { stage(s + 1); CP_WAIT1(); }
        else            { CP_WAIT0(); }
        __syncthreads();

        const uint32_t KHb = sb + ATT_B0 + (s & 1) * ATT_KVBUF;
        const uint32_t KLb = KHb + 8192, VHb = KHb + 16384, VLb = KHb + 24576;
        const uint32_t MSo = ATT_MS0 + (s & 1) * ATT_MSBUF;

        // --- S = Q K^T (3-pass split) ---
        float accS[8][4];
#pragma unroll
        for (int nf = 0; nf < 8; nf++)
#pragma unroll
            for (int e = 0; e < 4; e++) accS[nf][e] = 0.f;

#pragma unroll
        for (int kf = 0; kf < 4; kf++) {
            uint32_t qh[4], ql[4];
            {
                int row = w * 16 + (mat & 1) * 8 + r8;
                int chk = kf * 2 + (mat >> 1);
                uint32_t off = (uint32_t)(row * 128 + ((chk ^ (row & 7)) * 16));
                ldsm_x4(qh, sb + ATT_QH + off);
                ldsm_x4(ql, sb + ATT_QL + off);
            }
#pragma unroll
            for (int g = 0; g < 4; g++) {
                uint32_t kh[4], kl[4];
                int row = g * 16 + (mat >> 1) * 8 + r8;
                int chk = kf * 2 + (mat & 1);
                uint32_t off = (uint32_t)(row * 128 + ((chk ^ (row & 7)) * 16));
                ldsm_x4(kh, KHb + off);
                ldsm_x4(kl, KLb + off);
                mma_bf16(accS[2 * g],     qh, kh);
                mma_bf16(accS[2 * g],     qh, kl);
                mma_bf16(accS[2 * g],     ql, kh);
                mma_bf16(accS[2 * g + 1], qh, kh + 2);
                mma_bf16(accS[2 * g + 1], qh, kl + 2);
                mma_bf16(accS[2 * g + 1], ql, kh + 2);
            }
        }

        // --- softmax (fp32, log2 domain; MUFU ex2) ---
        const int rw0 = w * 16 + gr;
        float t0 = -3.0e38f, t1 = -3.0e38f;
#pragma unroll
        for (int nf = 0; nf < 8; nf++) {
            int colb = (nf * 8 + (l & 3) * 2) * 2;
            __nv_bfloat162 ms0 = *(__nv_bfloat162*)(smem + MSo + rw0 * 144 + colb);
            __nv_bfloat162 ms1 = *(__nv_bfloat162*)(smem + MSo + (rw0 + 8) * 144 + colb);
            accS[nf][0] = fmaf(accS[nf][0], SC, __bfloat162float(ms0.x));
            accS[nf][1] = fmaf(accS[nf][1], SC, __bfloat162float(ms0.y));
            accS[nf][2] = fmaf(accS[nf][2], SC, __bfloat162float(ms1.x));
            accS[nf][3] = fmaf(accS[nf][3], SC, __bfloat162float(ms1.y));
            t0 = fmaxf(t0, fmaxf(accS[nf][0], accS[nf][1]));
            t1 = fmaxf(t1, fmaxf(accS[nf][2], accS[nf][3]));
        }
        t0 = fmaxf(t0, __shfl_xor_sync(0xffffffffu, t0, 1));
        t0 = fmaxf(t0, __shfl_xor_sync(0xffffffffu, t0, 2));
        t1 = fmaxf(t1, __shfl_xor_sync(0xffffffffu, t1, 1));
        t1 = fmaxf(t1, __shfl_xor_sync(0xffffffffu, t1, 2));

        float mn0 = fmaxf(m0r, t0), mn1 = fmaxf(m1r, t1);
        float f0 = ex2f(m0r - mn0), f1 = ex2f(m1r - mn1);
        m0r = mn0; m1r = mn1;

        float rs0 = 0.f, rs1 = 0.f;
#pragma unroll
        for (int nf = 0; nf < 8; nf++) {
            accS[nf][0] = ex2f(accS[nf][0] - m0r);
            accS[nf][1] = ex2f(accS[nf][1] - m0r);
            accS[nf][2] = ex2f(accS[nf][2] - m1r);
            accS[nf][3] = ex2f(accS[nf][3] - m1r);
            rs0 += accS[nf][0] + accS[nf][1];
            rs1 += accS[nf][2] + accS[nf][3];
            accO[nf][0] *= f0; accO[nf][1] *= f0;
            accO[nf][2] *= f1; accO[nf][3] *= f1;
        }
        rs0 += __shfl_xor_sync(0xffffffffu, rs0, 1);
        rs0 += __shfl_xor_sync(0xffffffffu, rs0, 2);
        rs1 += __shfl_xor_sync(0xffffffffu, rs1, 1);
        rs1 += __shfl_xor_sync(0xffffffffu, rs1, 2);
        l0r = l0r * f0 + rs0;
        l1r = l1r * f1 + rs1;

        // --- O += P @ V (3-pass: Ph·Vh + Ph·Vl + Pl·Vh) ---
#pragma unroll
        for (int kf = 0; kf < 4; kf++) {
            const float* pA = accS[2 * kf];
            const float* pB = accS[2 * kf + 1];
            float ev[8] = {pA[0], pA[1], pA[2], pA[3], pB[0], pB[1], pB[2], pB[3]};
            uint32_t ah[4], al[4];
#pragma unroll
            for (int i = 0; i < 4; i++) {
                float x = ev[2 * i], y = ev[2 * i + 1];
                __nv_bfloat16 xh = __float2bfloat16_rn(x);
                __nv_bfloat16 yh = __float2bfloat16_rn(y);
                ah[i] = pack_bf16(x, y);
                al[i] = pack_bf16(x - __bfloat162float(xh),
                                  y - __bfloat162float(yh));
            }
            int rowv = kf * 16 + (l & 15);
#pragma unroll
            for (int g = 0; g < 4; g++) {
                uint32_t vh[4], vl[4];
                int chv = g * 2 + (l >> 4);
                uint32_t off = (uint32_t)(rowv * 128 + ((chv ^ (rowv & 7)) * 16));
                ldsm_x4_t(vh, VHb + off);
                ldsm_x4_t(vl, VLb + off);
                mma_bf16(accO[2 * g],     ah, vh);
                mma_bf16(accO[2 * g],     ah, vl);
                mma_bf16(accO[2 * g],     al, vh);
                mma_bf16(accO[2 * g + 1], ah, vh + 2);
                mma_bf16(accO[2 * g + 1], ah, vl + 2);
                mma_bf16(accO[2 * g + 1], al, vh + 2);
            }
        }
        __syncthreads();
    }

    // --- finalize: divide, split hi/lo, write Zh/Zl ---
    float inv0 = 1.f / l0r, inv1 = 1.f / l1r;
    int qg0 = q0 + w * 16 + gr;
#pragma unroll
    for (int nf = 0; nf < 8; nf++) {
        int d = nf * 8 + (l & 3) * 2;
        float x0 = accO[nf][0] * inv0, y0 = accO[nf][1] * inv0;
        float x1 = accO[nf][2] * inv1, y1 = accO[nf][3] * inv1;
        size_t i0 = ((size_t)(b * Lc + qg0)) * Cc + h * 64 + d;
        size_t i1 = ((size_t)(b * Lc + qg0 + 8)) * Cc + h * 64 + d;
        __nv_bfloat162 h0 = __floats2bfloat162_rn(x0, y0);
        __nv_bfloat162 l0 = __floats2bfloat162_rn(
            x0 - __bfloat162float(h0.x), y0 - __bfloat162float(h0.y));
        __nv_bfloat162 h1 = __floats2bfloat162_rn(x1, y1);
        __nv_bfloat162 l1 = __floats2bfloat162_rn(
            x1 - __bfloat162float(h1.x), y1 - __bfloat162float(h1.y));
        *(uint32_t*)&Zh[i0] = *(uint32_t*)&h0;
        *(uint32_t*)&Zl[i0] = *(uint32_t*)&l0;
        *(uint32_t*)&Zh[i1] = *(uint32_t*)&h1;
        *(uint32_t*)&Zl[i1] = *(uint32_t*)&l1;
    }
}

// ============================================================================
// Launcher
// ============================================================================
extern "C" void kernel_launch(void* const* d_in, const int* in_sizes, int n_in,
                              void* d_out, int out_size)
{
    const float* query = (const float*)d_in[0];
    const float* key_  = (const float*)d_in[1];
    const float* value = (const float*)d_in[2];
    const int*   mask  = (const int*)  d_in[3];
    const float* WQ = (const float*)d_in[4];
    const float* bQ = (const float*)d_in[5];
    const float* WK = (const float*)d_in[6];
    const float* bK = (const float*)d_in[7];
    const float* WV = (const float*)d_in[8];
    const float* bV = (const float*)d_in[9];
    const float* WO = (const float*)d_in[10];
    const float* bO = (const float*)d_in[11];
    float* out = (float*)d_out;

    void *xqh, *xql, *xkh, *xkl, *xvh, *xvl;
    cudaGetSymbolAddress(&xqh, g_Xq_h); cudaGetSymbolAddress(&xql, g_Xq_l);
    cudaGetSymbolAddress(&xkh, g_Xk_h); cudaGetSymbolAddress(&xkl, g_Xk_l);
    cudaGetSymbolAddress(&xvh, g_Xv_h); cudaGetSymbolAddress(&xvl, g_Xv_l);
    void *qbh, *qbl, *kbh, *kbl, *vbh, *vbl, *zh, *zl, *pM;
    cudaGetSymbolAddress(&qbh, g_Qb_h); cudaGetSymbolAddress(&qbl, g_Qb_l);
    cudaGetSymbolAddress(&kbh, g_Kb_h); cudaGetSymbolAddress(&kbl, g_Kb_l);
    cudaGetSymbolAddress(&vbh, g_Vb_h); cudaGetSymbolAddress(&vbl, g_Vb_l);
    cudaGetSymbolAddress(&zh, g_Zh);    cudaGetSymbolAddress(&zl, g_Zl);
    cudaGetSymbolAddress(&pM, g_Mb);
    void *wqh, *wql, *wkh, *wkl, *wvh, *wvl, *woh, *wol;
    cudaGetSymbolAddress(&wqh, g_WtQ_h); cudaGetSymbolAddress(&wql, g_WtQ_l);
    cudaGetSymbolAddress(&wkh, g_WtK_h); cudaGetSymbolAddress(&wkl, g_WtK_l);
    cudaGetSymbolAddress(&wvh, g_WtV_h); cudaGetSymbolAddress(&wvl, g_WtV_l);
    cudaGetSymbolAddress(&woh, g_WtO_h); cudaGetSymbolAddress(&wol, g_WtO_l);

    cudaFuncSetAttribute(attn_mma_kernel,
                         cudaFuncAttributeMaxDynamicSharedMemorySize, ATT_SMEM);
    cudaFuncSetAttribute(gemm_proj_kernel,
                         cudaFuncAttributeMaxDynamicSharedMemorySize, G_SMEM_TOTAL);
    cudaFuncSetAttribute(gemm_out_kernel,
                         cudaFuncAttributeMaxDynamicSharedMemorySize, G_SMEM_TOTAL);

    // --- Prep (fused) ---
    XSplitBatch xp;
    xp.X[0] = query; xp.X[1] = key_; xp.X[2] = value;
    xp.Xh[0] = (__nv_bfloat16*)xqh; xp.Xl[0] = (__nv_bfloat16*)xql;
    xp.Xh[1] = (__nv_bfloat16*)xkh; xp.Xl[1] = (__nv_bfloat16*)xkl;
    xp.Xh[2] = (__nv_bfloat16*)xvh; xp.Xl[2] = (__nv_bfloat16*)xvl;
    xsplit_kernel<<<dim3(Mc * Cc / (256 * 8), 3), 256>>>(xp);

    maskprep_kernel<<<(Bc * Lc * Lc) / (256 * 4), 256>>>(mask, (__nv_bfloat16*)pM);

    WSplitBatch wp;
    wp.W[0] = WQ; wp.W[1] = WK; wp.W[2] = WV; wp.W[3] = WO;
    wp.Th[0] = (__nv_bfloat16*)wqh; wp.Tl[0] = (__nv_bfloat16*)wql;
    wp.Th[1] = (__nv_bfloat16*)wkh; wp.Tl[1] = (__nv_bfloat16*)wkl;
    wp.Th[2] = (__nv_bfloat16*)wvh; wp.Tl[2] = (__nv_bfloat16*)wvl;
    wp.Th[3] = (__nv_bfloat16*)woh; wp.Tl[3] = (__nv_bfloat16*)wol;
    wsplit_kernel<<<dim3(32, 32, 4), dim3(32, 8)>>>(wp);

    // --- Fused projection GEMMs (grid.z = 3) ---
    GemmBatch gp;
    gp.Ah[0] = (const __nv_bfloat16*)xqh; gp.Al[0] = (const __nv_bfloat16*)xql;
    gp.Ah[1] = (const __nv_bfloat16*)xkh; gp.Al[1] = (const __nv_bfloat16*)xkl;
    gp.Ah[2] = (const __nv_bfloat16*)xvh; gp.Al[2] = (const __nv_bfloat16*)xvl;
    gp.Bh[0] = (const __nv_bfloat16*)wqh; gp.Bl[0] = (const __nv_bfloat16*)wql;
    gp.Bh[1] = (const __nv_bfloat16*)wkh; gp.Bl[1] = (const __nv_bfloat16*)wkl;
    gp.Bh[2] = (const __nv_bfloat16*)wvh; gp.Bl[2] = (const __nv_bfloat16*)wvl;
    gp.bias[0] = bQ; gp.bias[1] = bK; gp.bias[2] = bV;
    gp.Yh[0] = (__nv_bfloat16*)qbh; gp.Yl[0] = (__nv_bfloat16*)qbl;
    gp.Yh[1] = (__nv_bfloat16*)kbh; gp.Yl[1] = (__nv_bfloat16*)kbl;
    gp.Yh[2] = (__nv_bfloat16*)vbh; gp.Yl[2] = (__nv_bfloat16*)vbl;
    gemm_proj_kernel<<<dim3(Cc / 128, Mc / 128, 3), 256, G_SMEM_TOTAL>>>(gp);

    dim3 attn_grid(Lc / 128, Bc * Hc);
    attn_mma_kernel<<<attn_grid, 256, ATT_SMEM>>>(
        (const __nv_bfloat16*)qbh, (const __nv_bfloat16*)qbl,
        (const __nv_bfloat16*)kbh, (const __nv_bfloat16*)kbl,
        (const __nv_bfloat16*)vbh, (const __nv_bfloat16*)vbl,
        (const __nv_bfloat16*)pM, (__nv_bfloat16*)zh, (__nv_bfloat16*)zl);

    gemm_out_kernel<<<dim3(Cc / 128, Mc / 128), 256, G_SMEM_TOTAL>>>(
        (const __nv_bfloat16*)zh, (const __nv_bfloat16*)zl,
        (const __nv_bfloat16*)woh, (const __nv_bfloat16*)wol, bO, out);
}